// round 2
// baseline (speedup 1.0000x reference)
#include <cuda_runtime.h>
#include <cuda_bf16.h>
#include <math.h>

// Problem constants
#define DHID 1024
#define DA   512
#define BB   16
#define LL   2048
#define RR   64
#define MTOT (BB*LL)   // 32768

// ---------------------------------------------------------------------------
// Scratch (static device globals; no allocations allowed)
// ---------------------------------------------------------------------------
__device__ float g_qk[(size_t)MTOT * DA];     // 64 MiB
__device__ float g_u [(size_t)MTOT * DHID];   // 128 MiB
__device__ float g_y [(size_t)MTOT * DHID];   // 128 MiB
__device__ float g_A [DA * DHID];             // fused qk_W1 @ q_W
__device__ float g_Bm[DA * DHID];             // fused qk_W2 @ k_W
__device__ float g_c [DA];                    // fused bias

// ---------------------------------------------------------------------------
// GEMM (NT): C[m,n] = sum_k X1[m,k]*W1[n,k] (+ X2[m,k]*W2[n,k]) + bias[n]
// X: (M,K) row-major; W: (N,K) row-major. 128x128x16 tile, 8x8 micro.
// ---------------------------------------------------------------------------
#define BM 128
#define BN 128
#define BK 16

__global__ void __launch_bounds__(256, 2) gemm_nt_kernel(
    float* __restrict__ C,
    const float* __restrict__ X1, const float* __restrict__ W1,
    const float* __restrict__ X2, const float* __restrict__ W2,
    const float* __restrict__ bias,
    int M, int N, int K)
{
    __shared__ float As[BK][BM];
    __shared__ float Bs[BK][BN];
    const int t  = threadIdx.x;
    const int bm = blockIdx.y * BM;
    const int bn = blockIdx.x * BN;

    float acc[8][8];
    #pragma unroll
    for (int i = 0; i < 8; ++i)
        #pragma unroll
        for (int j = 0; j < 8; ++j) acc[i][j] = 0.f;

    const int lrow = t >> 2;          // 0..63
    const int lc4  = (t & 3) * 4;     // 0,4,8,12

    for (int phase = 0; phase < 2; ++phase) {
        const float* X = phase ? X2 : X1;
        const float* W = phase ? W2 : W1;
        if (!X) break;
        for (int k0 = 0; k0 < K; k0 += BK) {
            #pragma unroll
            for (int h = 0; h < 2; ++h) {
                int row = lrow + h * 64;
                float4 v = *(const float4*)&X[(size_t)(bm + row) * K + k0 + lc4];
                As[lc4 + 0][row] = v.x;
                As[lc4 + 1][row] = v.y;
                As[lc4 + 2][row] = v.z;
                As[lc4 + 3][row] = v.w;
                float4 w = *(const float4*)&W[(size_t)(bn + row) * K + k0 + lc4];
                Bs[lc4 + 0][row] = w.x;
                Bs[lc4 + 1][row] = w.y;
                Bs[lc4 + 2][row] = w.z;
                Bs[lc4 + 3][row] = w.w;
            }
            __syncthreads();
            const int m8 = (t >> 4) * 8;
            const int n8 = (t & 15) * 8;
            #pragma unroll
            for (int kk = 0; kk < BK; ++kk) {
                float a[8], b[8];
                *(float4*)&a[0] = *(const float4*)&As[kk][m8];
                *(float4*)&a[4] = *(const float4*)&As[kk][m8 + 4];
                *(float4*)&b[0] = *(const float4*)&Bs[kk][n8];
                *(float4*)&b[4] = *(const float4*)&Bs[kk][n8 + 4];
                #pragma unroll
                for (int i = 0; i < 8; ++i)
                    #pragma unroll
                    for (int j = 0; j < 8; ++j)
                        acc[i][j] += a[i] * b[j];
            }
            __syncthreads();
        }
    }

    const int m0 = bm + (t >> 4) * 8;
    const int n0 = bn + (t & 15) * 8;
    float bj[8];
    #pragma unroll
    for (int j = 0; j < 8; ++j) bj[j] = bias ? bias[n0 + j] : 0.f;
    #pragma unroll
    for (int i = 0; i < 8; ++i) {
        float4 o0, o1;
        o0.x = acc[i][0] + bj[0]; o0.y = acc[i][1] + bj[1];
        o0.z = acc[i][2] + bj[2]; o0.w = acc[i][3] + bj[3];
        o1.x = acc[i][4] + bj[4]; o1.y = acc[i][5] + bj[5];
        o1.z = acc[i][6] + bj[6]; o1.w = acc[i][7] + bj[7];
        *(float4*)&C[(size_t)(m0 + i) * N + n0]     = o0;
        *(float4*)&C[(size_t)(m0 + i) * N + n0 + 4] = o1;
    }
}

// ---------------------------------------------------------------------------
// GEMM (NN): C[m,n] = sum_k X[m*ldx + k] * W[k*N + n]  (+ bias[n] if non-null)
// W is (K,N) row-major (N contiguous). Same tiling as NT.
// ---------------------------------------------------------------------------
__global__ void __launch_bounds__(256, 2) gemm_nn_kernel(
    float* __restrict__ C,
    const float* __restrict__ X, const float* __restrict__ W,
    const float* __restrict__ bias,
    int M, int N, int K, int ldx)
{
    __shared__ float As[BK][BM];
    __shared__ float Bs[BK][BN];
    const int t  = threadIdx.x;
    const int bm = blockIdx.y * BM;
    const int bn = blockIdx.x * BN;

    float acc[8][8];
    #pragma unroll
    for (int i = 0; i < 8; ++i)
        #pragma unroll
        for (int j = 0; j < 8; ++j) acc[i][j] = 0.f;

    const int lrow = t >> 2;          // 0..63  (X loader)
    const int lc4  = (t & 3) * 4;
    const int wk   = t >> 5;          // 0..7   (W loader)
    const int wn4  = (t & 31) * 4;    // 0..124

    for (int k0 = 0; k0 < K; k0 += BK) {
        #pragma unroll
        for (int h = 0; h < 2; ++h) {
            int row = lrow + h * 64;
            float4 v = *(const float4*)&X[(size_t)(bm + row) * ldx + k0 + lc4];
            As[lc4 + 0][row] = v.x;
            As[lc4 + 1][row] = v.y;
            As[lc4 + 2][row] = v.z;
            As[lc4 + 3][row] = v.w;
            int k = wk + h * 8;
            float4 w = *(const float4*)&W[(size_t)(k0 + k) * N + bn + wn4];
            *(float4*)&Bs[k][wn4] = w;
        }
        __syncthreads();
        const int m8 = (t >> 4) * 8;
        const int n8 = (t & 15) * 8;
        #pragma unroll
        for (int kk = 0; kk < BK; ++kk) {
            float a[8], b[8];
            *(float4*)&a[0] = *(const float4*)&As[kk][m8];
            *(float4*)&a[4] = *(const float4*)&As[kk][m8 + 4];
            *(float4*)&b[0] = *(const float4*)&Bs[kk][n8];
            *(float4*)&b[4] = *(const float4*)&Bs[kk][n8 + 4];
            #pragma unroll
            for (int i = 0; i < 8; ++i)
                #pragma unroll
                for (int j = 0; j < 8; ++j)
                    acc[i][j] += a[i] * b[j];
        }
        __syncthreads();
    }

    const int m0 = bm + (t >> 4) * 8;
    const int n0 = bn + (t & 15) * 8;
    float bj[8];
    #pragma unroll
    for (int j = 0; j < 8; ++j) bj[j] = bias ? bias[n0 + j] : 0.f;
    #pragma unroll
    for (int i = 0; i < 8; ++i) {
        float4 o0, o1;
        o0.x = acc[i][0] + bj[0]; o0.y = acc[i][1] + bj[1];
        o0.z = acc[i][2] + bj[2]; o0.w = acc[i][3] + bj[3];
        o1.x = acc[i][4] + bj[4]; o1.y = acc[i][5] + bj[5];
        o1.z = acc[i][6] + bj[6]; o1.w = acc[i][7] + bj[7];
        *(float4*)&C[(size_t)(m0 + i) * N + n0]     = o0;
        *(float4*)&C[(size_t)(m0 + i) * N + n0 + 4] = o1;
    }
}

// ---------------------------------------------------------------------------
// Fused bias: c[i] = sum_j qk_W[i,j]*q_b[j] + qk_W[i,512+j]*k_b[j] + qk_b[i]
// ---------------------------------------------------------------------------
__global__ void fuse_bias_kernel(float* __restrict__ c,
                                 const float* __restrict__ qk_W,
                                 const float* __restrict__ q_b,
                                 const float* __restrict__ k_b,
                                 const float* __restrict__ qk_b)
{
    int i = blockIdx.x * blockDim.x + threadIdx.x;
    if (i >= DA) return;
    float s = qk_b[i];
    const float* row = qk_W + (size_t)i * (2 * DA);
    for (int j = 0; j < DA; ++j)
        s += row[j] * q_b[j] + row[DA + j] * k_b[j];
    c[i] = s;
}

// ---------------------------------------------------------------------------
// Attention: one block per l.
//   scores[b,r] = scale * <u[b,l,:], basis[l,r,:]>
//   w = softmax_r(scores)
//   y[b,l,:]    = sum_r w[b,r] * basis[l,r,:]
// ---------------------------------------------------------------------------
#define SS_LD 65   // padded row for scores in smem

__global__ void __launch_bounds__(256) attention_kernel(
    const float* __restrict__ u,      // (B*L, 1024)
    const float* __restrict__ basis,  // (L, R, 1024)
    float* __restrict__ y)            // (B*L, 1024)
{
    extern __shared__ float sm[];
    float* u_s = sm;                       // 16 * 1024
    float* s_s = sm + BB * DHID;           // 16 * SS_LD

    const int l    = blockIdx.x;
    const int t    = threadIdx.x;
    const int warp = t >> 5;
    const int lane = t & 31;
    const float scale = 0.044194173824159216f;  // 1/sqrt(512)

    // Load u tile (16 rows of 1024) into smem
    for (int idx = t; idx < BB * DHID / 4; idx += 256) {
        int b  = idx >> 8;         // 256 float4 per row
        int d4 = idx & 255;
        *(float4*)&u_s[b * DHID + d4 * 4] =
            *(const float4*)&u[((size_t)b * LL + l) * DHID + d4 * 4];
    }
    __syncthreads();

    const float* basl = basis + (size_t)l * RR * DHID;

    // Phase 1: scores
    for (int rr = 0; rr < 8; ++rr) {
        int r = warp * 8 + rr;
        const float* brow = basl + (size_t)r * DHID;
        float bas[32];
        #pragma unroll
        for (int i = 0; i < 32; ++i) bas[i] = brow[lane + 32 * i];
        #pragma unroll
        for (int b = 0; b < BB; ++b) {
            float p = 0.f;
            const float* ur = &u_s[b * DHID];
            #pragma unroll
            for (int i = 0; i < 32; ++i) p += bas[i] * ur[lane + 32 * i];
            #pragma unroll
            for (int o = 16; o; o >>= 1) p += __shfl_xor_sync(0xffffffffu, p, o);
            if (lane == 0) s_s[b * SS_LD + r] = p * scale;
        }
    }
    __syncthreads();

    // Phase 2: softmax over r (64 values per b); warp w handles b = 2w, 2w+1
    {
        int b0 = warp * 2;
        #pragma unroll
        for (int bi = 0; bi < 2; ++bi) {
            int b = b0 + bi;
            float v0 = s_s[b * SS_LD + lane];
            float v1 = s_s[b * SS_LD + lane + 32];
            float mx = fmaxf(v0, v1);
            #pragma unroll
            for (int o = 16; o; o >>= 1) mx = fmaxf(mx, __shfl_xor_sync(0xffffffffu, mx, o));
            float e0 = __expf(v0 - mx);
            float e1 = __expf(v1 - mx);
            float sum = e0 + e1;
            #pragma unroll
            for (int o = 16; o; o >>= 1) sum += __shfl_xor_sync(0xffffffffu, sum, o);
            float inv = 1.f / sum;
            s_s[b * SS_LD + lane]      = e0 * inv;
            s_s[b * SS_LD + lane + 32] = e1 * inv;
        }
    }
    __syncthreads();

    // Phase 3: y accumulation
    for (int i = 0; i < 4; ++i) {
        int d = i * 256 + t;
        float acc[BB];
        #pragma unroll
        for (int b = 0; b < BB; ++b) acc[b] = 0.f;
        #pragma unroll 4
        for (int r = 0; r < RR; ++r) {
            float bv = basl[(size_t)r * DHID + d];
            #pragma unroll
            for (int b = 0; b < BB; ++b)
                acc[b] += s_s[b * SS_LD + r] * bv;
        }
        #pragma unroll
        for (int b = 0; b < BB; ++b)
            y[((size_t)b * LL + l) * DHID + d] = acc[b];
    }
}

// ---------------------------------------------------------------------------
// Launch
// ---------------------------------------------------------------------------
extern "C" void kernel_launch(void* const* d_in, const int* in_sizes, int n_in,
                              void* d_out, int out_size)
{
    const float* s_emb  = (const float*)d_in[0];
    const float* t_emb  = (const float*)d_in[1];
    const float* basis  = (const float*)d_in[2];
    const float* q_W    = (const float*)d_in[3];
    const float* q_b    = (const float*)d_in[4];
    const float* k_W    = (const float*)d_in[5];
    const float* k_b    = (const float*)d_in[6];
    const float* qk_W   = (const float*)d_in[7];
    const float* qk_b   = (const float*)d_in[8];
    const float* bk_W   = (const float*)d_in[9];
    // d_in[10] = bk_b : provably unused (softmax shift invariance)
    const float* bv_W   = (const float*)d_in[11];
    const float* bv_b   = (const float*)d_in[12];
    float* out = (float*)d_out;

    float *p_qk, *p_u, *p_y, *p_A, *p_Bm, *p_c;
    cudaGetSymbolAddress((void**)&p_qk, g_qk);
    cudaGetSymbolAddress((void**)&p_u,  g_u);
    cudaGetSymbolAddress((void**)&p_y,  g_y);
    cudaGetSymbolAddress((void**)&p_A,  g_A);
    cudaGetSymbolAddress((void**)&p_Bm, g_Bm);
    cudaGetSymbolAddress((void**)&p_c,  g_c);

    const int att_smem = (BB * DHID + BB * SS_LD) * (int)sizeof(float);
    cudaFuncSetAttribute(attention_kernel,
                         cudaFuncAttributeMaxDynamicSharedMemorySize, att_smem);

    // 1) Fused projection matrices: A = qk_W[:, :512] @ q_W ; Bm = qk_W[:, 512:] @ k_W
    {
        dim3 grid(DHID / BN, DA / BM);
        gemm_nn_kernel<<<grid, 256>>>(p_A,  qk_W,       q_W, nullptr, DA, DHID, DA, 2 * DA);
        gemm_nn_kernel<<<grid, 256>>>(p_Bm, qk_W + DA,  k_W, nullptr, DA, DHID, DA, 2 * DA);
        fuse_bias_kernel<<<1, DA>>>(p_c, qk_W, q_b, k_b, qk_b);
    }

    // 2) qk = s @ A^T + t @ Bm^T + c       (32768 x 512, K=1024)
    {
        dim3 grid(DA / BN, MTOT / BM);
        gemm_nt_kernel<<<grid, 256>>>(p_qk, s_emb, p_A, t_emb, p_Bm, p_c,
                                      MTOT, DA, DHID);
    }

    // 3) u = qk @ bk_W                      (32768 x 1024, K=512)
    {
        dim3 grid(DHID / BN, MTOT / BM);
        gemm_nn_kernel<<<grid, 256>>>(p_u, p_qk, bk_W, nullptr, MTOT, DHID, DA, DA);
    }

    // 4) attention: scores -> softmax -> y  (one block per l)
    attention_kernel<<<LL, 256, att_smem>>>(p_u, basis, p_y);

    // 5) z = y @ bv_W^T + bv_b              (32768 x 512, K=1024)
    {
        dim3 grid(DA / BN, MTOT / BM);
        gemm_nt_kernel<<<grid, 256>>>(out, p_y, bv_W, nullptr, nullptr, bv_b,
                                      MTOT, DA, DHID);
    }
}

// round 3
// speedup vs baseline: 1.9723x; 1.9723x over previous
#include <cuda_runtime.h>
#include <cuda_bf16.h>
#include <math.h>

// Problem constants
#define DHID 1024
#define DA   512
#define BB   16
#define LL   2048
#define RR   64
#define MTOT (BB*LL)   // 32768

// ---------------------------------------------------------------------------
// Scratch (static device globals; no allocations allowed)
// ---------------------------------------------------------------------------
__device__ float g_qk [(size_t)MTOT * DA];     // 64 MiB
__device__ float g_u  [(size_t)MTOT * DHID];   // 128 MiB
__device__ float g_y  [(size_t)MTOT * DHID];   // 128 MiB
__device__ float g_A  [DA * DHID];             // fused qk_W1 @ q_W   (512,1024)
__device__ float g_Bm [DA * DHID];             // fused qk_W2 @ k_W   (512,1024)
__device__ float g_c  [DA];                    // fused bias
__device__ float g_bkT[DHID * DA];             // bk_W transposed     (1024,512)

// ---------------------------------------------------------------------------
// bf16x3 tensor-core GEMM (NT):
//   C[m,n] = sum_k X1[m,k]*W1[n,k] (+ X2[m,k]*W2[n,k]) + bias[n]
// X: (M,K) row-major; W: (N,K) row-major.
// Each fp32 value is split x = hi + lo (both bf16); product computed as
// hi*hi + hi*lo + lo*hi  (3 mma passes) -> ~fp32 precision.
// Block tile 128x128x32, 8 warps, warp tile 64x32 (m16n8k16 micro-tiles).
// ---------------------------------------------------------------------------
#define SMS 40   // smem row stride in bf16 elements (conflict-free, verified)

__device__ __forceinline__ void mma_bf16(float* c, const unsigned* a, const unsigned* b)
{
    asm volatile(
        "mma.sync.aligned.m16n8k16.row.col.f32.bf16.bf16.f32 "
        "{%0,%1,%2,%3}, {%4,%5,%6,%7}, {%8,%9}, {%0,%1,%2,%3};\n"
        : "+f"(c[0]), "+f"(c[1]), "+f"(c[2]), "+f"(c[3])
        : "r"(a[0]), "r"(a[1]), "r"(a[2]), "r"(a[3]), "r"(b[0]), "r"(b[1]));
}

__device__ __forceinline__ void cvt_store4(unsigned short* hi, unsigned short* lo,
                                           int off, float4 v)
{
    __nv_bfloat162 h01 = __floats2bfloat162_rn(v.x, v.y);
    __nv_bfloat162 h23 = __floats2bfloat162_rn(v.z, v.w);
    float2 f01 = __bfloat1622float2(h01);
    float2 f23 = __bfloat1622float2(h23);
    __nv_bfloat162 l01 = __floats2bfloat162_rn(v.x - f01.x, v.y - f01.y);
    __nv_bfloat162 l23 = __floats2bfloat162_rn(v.z - f23.x, v.w - f23.y);
    *(__nv_bfloat162*)(hi + off)     = h01;
    *(__nv_bfloat162*)(hi + off + 2) = h23;
    *(__nv_bfloat162*)(lo + off)     = l01;
    *(__nv_bfloat162*)(lo + off + 2) = l23;
}

#define LDSU(arr, off) (*(const unsigned*)&(arr)[(off)])

__global__ void __launch_bounds__(256, 1) gemm_nt_bf16x3_kernel(
    float* __restrict__ C,
    const float* __restrict__ X1, const float* __restrict__ W1,
    const float* __restrict__ X2, const float* __restrict__ W2,
    const float* __restrict__ bias,
    int M, int N, int K)
{
    __shared__ __align__(16) unsigned short As_hi[128 * SMS];
    __shared__ __align__(16) unsigned short As_lo[128 * SMS];
    __shared__ __align__(16) unsigned short Bs_hi[128 * SMS];
    __shared__ __align__(16) unsigned short Bs_lo[128 * SMS];

    const int t    = threadIdx.x;
    const int bm   = blockIdx.y * 128;
    const int bn   = blockIdx.x * 128;
    const int warp = t >> 5;
    const int lane = t & 31;
    const int g    = lane >> 2;   // 0..7
    const int q    = lane & 3;    // 0..3
    const int m0   = (warp & 1) * 64;
    const int n0   = (warp >> 1) * 32;

    float acc[4][4][4];
    #pragma unroll
    for (int i = 0; i < 4; ++i)
        #pragma unroll
        for (int j = 0; j < 4; ++j)
            #pragma unroll
            for (int e = 0; e < 4; ++e) acc[i][j][e] = 0.f;

    const int lr = t >> 3;        // 0..31 (loader row)
    const int lc = (t & 7) * 4;   // 0..28 (loader col, 4 floats)

    for (int phase = 0; phase < 2; ++phase) {
        const float* X = phase ? X2 : X1;
        const float* W = phase ? W2 : W1;
        if (!X) break;

        float4 xr[4], wr[4];
        #pragma unroll
        for (int h = 0; h < 4; ++h) {
            xr[h] = *(const float4*)&X[(size_t)(bm + lr + 32 * h) * K + lc];
            wr[h] = *(const float4*)&W[(size_t)(bn + lr + 32 * h) * K + lc];
        }
        #pragma unroll
        for (int h = 0; h < 4; ++h) {
            int off = (lr + 32 * h) * SMS + lc;
            cvt_store4(As_hi, As_lo, off, xr[h]);
            cvt_store4(Bs_hi, Bs_lo, off, wr[h]);
        }
        __syncthreads();

        for (int k0 = 0; k0 < K; k0 += 32) {
            const bool more = (k0 + 32 < K);
            if (more) {
                #pragma unroll
                for (int h = 0; h < 4; ++h) {
                    xr[h] = *(const float4*)&X[(size_t)(bm + lr + 32 * h) * K + k0 + 32 + lc];
                    wr[h] = *(const float4*)&W[(size_t)(bn + lr + 32 * h) * K + k0 + 32 + lc];
                }
            }

            #pragma unroll
            for (int s = 0; s < 2; ++s) {
                const int kb = s * 16;
                unsigned ah[4][4], al[4][4], bh[4][2], bl[4][2];
                #pragma unroll
                for (int i = 0; i < 4; ++i) {
                    int o0 = (m0 + i * 16 + g) * SMS + kb + 2 * q;
                    int o1 = o0 + 8 * SMS;
                    ah[i][0] = LDSU(As_hi, o0);     ah[i][1] = LDSU(As_hi, o1);
                    ah[i][2] = LDSU(As_hi, o0 + 8); ah[i][3] = LDSU(As_hi, o1 + 8);
                    al[i][0] = LDSU(As_lo, o0);     al[i][1] = LDSU(As_lo, o1);
                    al[i][2] = LDSU(As_lo, o0 + 8); al[i][3] = LDSU(As_lo, o1 + 8);
                }
                #pragma unroll
                for (int j = 0; j < 4; ++j) {
                    int o = (n0 + j * 8 + g) * SMS + kb + 2 * q;
                    bh[j][0] = LDSU(Bs_hi, o); bh[j][1] = LDSU(Bs_hi, o + 8);
                    bl[j][0] = LDSU(Bs_lo, o); bl[j][1] = LDSU(Bs_lo, o + 8);
                }
                #pragma unroll
                for (int i = 0; i < 4; ++i)
                    #pragma unroll
                    for (int j = 0; j < 4; ++j) {
                        mma_bf16(acc[i][j], ah[i], bh[j]);
                        mma_bf16(acc[i][j], ah[i], bl[j]);
                        mma_bf16(acc[i][j], al[i], bh[j]);
                    }
            }
            __syncthreads();
            if (more) {
                #pragma unroll
                for (int h = 0; h < 4; ++h) {
                    int off = (lr + 32 * h) * SMS + lc;
                    cvt_store4(As_hi, As_lo, off, xr[h]);
                    cvt_store4(Bs_hi, Bs_lo, off, wr[h]);
                }
                __syncthreads();
            }
        }
    }

    // Epilogue
    #pragma unroll
    for (int i = 0; i < 4; ++i) {
        #pragma unroll
        for (int j = 0; j < 4; ++j) {
            int r = bm + m0 + i * 16 + g;
            int c = bn + n0 + j * 8 + 2 * q;
            float b0 = bias ? bias[c]     : 0.f;
            float b1 = bias ? bias[c + 1] : 0.f;
            float2 v0 = make_float2(acc[i][j][0] + b0, acc[i][j][1] + b1);
            float2 v1 = make_float2(acc[i][j][2] + b0, acc[i][j][3] + b1);
            *(float2*)&C[(size_t)r * N + c]       = v0;
            *(float2*)&C[(size_t)(r + 8) * N + c] = v1;
        }
    }
}

// ---------------------------------------------------------------------------
// Transpose: out (Ccols x Rrows) = in^T, in is (Rrows x Ccols)
// Used once for bk_W (512x1024 -> 1024x512).
// ---------------------------------------------------------------------------
__global__ void transpose_kernel(float* __restrict__ out, const float* __restrict__ in,
                                 int Rrows, int Ccols)
{
    __shared__ float tile[32][33];
    int x = blockIdx.x * 32 + threadIdx.x;
    int y = blockIdx.y * 32 + threadIdx.y;
    #pragma unroll
    for (int i = 0; i < 4; ++i)
        tile[threadIdx.y + 8 * i][threadIdx.x] = in[(size_t)(y + 8 * i) * Ccols + x];
    __syncthreads();
    x = blockIdx.y * 32 + threadIdx.x;
    y = blockIdx.x * 32 + threadIdx.y;
    #pragma unroll
    for (int i = 0; i < 4; ++i)
        out[(size_t)(y + 8 * i) * Rrows + x] = tile[threadIdx.x][threadIdx.y + 8 * i];
}

// ---------------------------------------------------------------------------
// fp32 SIMT GEMM (NN) — used only for the two small 512x1024x512 prep GEMMs.
// C[m,n] = sum_k X[m*ldx + k] * W[k*N + n]
// ---------------------------------------------------------------------------
#define BM 128
#define BN 128
#define BK 16

__global__ void __launch_bounds__(256, 2) gemm_nn_kernel(
    float* __restrict__ C,
    const float* __restrict__ X, const float* __restrict__ W,
    const float* __restrict__ bias,
    int M, int N, int K, int ldx)
{
    __shared__ float As[BK][BM];
    __shared__ float Bs[BK][BN];
    const int t  = threadIdx.x;
    const int bm = blockIdx.y * BM;
    const int bn = blockIdx.x * BN;

    float acc[8][8];
    #pragma unroll
    for (int i = 0; i < 8; ++i)
        #pragma unroll
        for (int j = 0; j < 8; ++j) acc[i][j] = 0.f;

    const int lrow = t >> 2;
    const int lc4  = (t & 3) * 4;
    const int wk   = t >> 5;
    const int wn4  = (t & 31) * 4;

    for (int k0 = 0; k0 < K; k0 += BK) {
        #pragma unroll
        for (int h = 0; h < 2; ++h) {
            int row = lrow + h * 64;
            float4 v = *(const float4*)&X[(size_t)(bm + row) * ldx + k0 + lc4];
            As[lc4 + 0][row] = v.x;
            As[lc4 + 1][row] = v.y;
            As[lc4 + 2][row] = v.z;
            As[lc4 + 3][row] = v.w;
            int k = wk + h * 8;
            float4 w = *(const float4*)&W[(size_t)(k0 + k) * N + bn + wn4];
            *(float4*)&Bs[k][wn4] = w;
        }
        __syncthreads();
        const int m8 = (t >> 4) * 8;
        const int n8 = (t & 15) * 8;
        #pragma unroll
        for (int kk = 0; kk < BK; ++kk) {
            float a[8], b[8];
            *(float4*)&a[0] = *(const float4*)&As[kk][m8];
            *(float4*)&a[4] = *(const float4*)&As[kk][m8 + 4];
            *(float4*)&b[0] = *(const float4*)&Bs[kk][n8];
            *(float4*)&b[4] = *(const float4*)&Bs[kk][n8 + 4];
            #pragma unroll
            for (int i = 0; i < 8; ++i)
                #pragma unroll
                for (int j = 0; j < 8; ++j)
                    acc[i][j] += a[i] * b[j];
        }
        __syncthreads();
    }

    const int m0 = bm + (t >> 4) * 8;
    const int n0 = bn + (t & 15) * 8;
    float bj[8];
    #pragma unroll
    for (int j = 0; j < 8; ++j) bj[j] = bias ? bias[n0 + j] : 0.f;
    #pragma unroll
    for (int i = 0; i < 8; ++i) {
        float4 o0, o1;
        o0.x = acc[i][0] + bj[0]; o0.y = acc[i][1] + bj[1];
        o0.z = acc[i][2] + bj[2]; o0.w = acc[i][3] + bj[3];
        o1.x = acc[i][4] + bj[4]; o1.y = acc[i][5] + bj[5];
        o1.z = acc[i][6] + bj[6]; o1.w = acc[i][7] + bj[7];
        *(float4*)&C[(size_t)(m0 + i) * N + n0]     = o0;
        *(float4*)&C[(size_t)(m0 + i) * N + n0 + 4] = o1;
    }
}

// ---------------------------------------------------------------------------
// Fused bias: c[i] = sum_j qk_W[i,j]*q_b[j] + qk_W[i,512+j]*k_b[j] + qk_b[i]
// ---------------------------------------------------------------------------
__global__ void fuse_bias_kernel(float* __restrict__ c,
                                 const float* __restrict__ qk_W,
                                 const float* __restrict__ q_b,
                                 const float* __restrict__ k_b,
                                 const float* __restrict__ qk_b)
{
    int i = blockIdx.x * blockDim.x + threadIdx.x;
    if (i >= DA) return;
    float s = qk_b[i];
    const float* row = qk_W + (size_t)i * (2 * DA);
    for (int j = 0; j < DA; ++j)
        s += row[j] * q_b[j] + row[DA + j] * k_b[j];
    c[i] = s;
}

// ---------------------------------------------------------------------------
// Attention: one block per l.
//   scores[b,r] = scale * <u[b,l,:], basis[l,r,:]>
//   w = softmax_r(scores);  y[b,l,:] = sum_r w[b,r] * basis[l,r,:]
// ---------------------------------------------------------------------------
#define SS_LD 65

__global__ void __launch_bounds__(256) attention_kernel(
    const float* __restrict__ u,      // (B*L, 1024)
    const float* __restrict__ basis,  // (L, R, 1024)
    float* __restrict__ y)            // (B*L, 1024)
{
    extern __shared__ float sm[];
    float* u_s = sm;                       // 16 * 1024
    float* s_s = sm + BB * DHID;           // 16 * SS_LD

    const int l    = blockIdx.x;
    const int t    = threadIdx.x;
    const int warp = t >> 5;
    const int lane = t & 31;
    const float scale = 0.044194173824159216f;  // 1/sqrt(512)

    for (int idx = t; idx < BB * DHID / 4; idx += 256) {
        int b  = idx >> 8;
        int d4 = idx & 255;
        *(float4*)&u_s[b * DHID + d4 * 4] =
            *(const float4*)&u[((size_t)b * LL + l) * DHID + d4 * 4];
    }
    __syncthreads();

    const float* basl = basis + (size_t)l * RR * DHID;

    for (int rr = 0; rr < 8; ++rr) {
        int r = warp * 8 + rr;
        const float* brow = basl + (size_t)r * DHID;
        float bas[32];
        #pragma unroll
        for (int i = 0; i < 32; ++i) bas[i] = brow[lane + 32 * i];
        #pragma unroll
        for (int b = 0; b < BB; ++b) {
            float p = 0.f;
            const float* ur = &u_s[b * DHID];
            #pragma unroll
            for (int i = 0; i < 32; ++i) p += bas[i] * ur[lane + 32 * i];
            #pragma unroll
            for (int o = 16; o; o >>= 1) p += __shfl_xor_sync(0xffffffffu, p, o);
            if (lane == 0) s_s[b * SS_LD + r] = p * scale;
        }
    }
    __syncthreads();

    {
        int b0 = warp * 2;
        #pragma unroll
        for (int bi = 0; bi < 2; ++bi) {
            int b = b0 + bi;
            float v0 = s_s[b * SS_LD + lane];
            float v1 = s_s[b * SS_LD + lane + 32];
            float mx = fmaxf(v0, v1);
            #pragma unroll
            for (int o = 16; o; o >>= 1) mx = fmaxf(mx, __shfl_xor_sync(0xffffffffu, mx, o));
            float e0 = __expf(v0 - mx);
            float e1 = __expf(v1 - mx);
            float sum = e0 + e1;
            #pragma unroll
            for (int o = 16; o; o >>= 1) sum += __shfl_xor_sync(0xffffffffu, sum, o);
            float inv = 1.f / sum;
            s_s[b * SS_LD + lane]      = e0 * inv;
            s_s[b * SS_LD + lane + 32] = e1 * inv;
        }
    }
    __syncthreads();

    for (int i = 0; i < 4; ++i) {
        int d = i * 256 + t;
        float acc[BB];
        #pragma unroll
        for (int b = 0; b < BB; ++b) acc[b] = 0.f;
        #pragma unroll 4
        for (int r = 0; r < RR; ++r) {
            float bv = basl[(size_t)r * DHID + d];
            #pragma unroll
            for (int b = 0; b < BB; ++b)
                acc[b] += s_s[b * SS_LD + r] * bv;
        }
        #pragma unroll
        for (int b = 0; b < BB; ++b)
            y[((size_t)b * LL + l) * DHID + d] = acc[b];
    }
}

// ---------------------------------------------------------------------------
// Launch
// ---------------------------------------------------------------------------
extern "C" void kernel_launch(void* const* d_in, const int* in_sizes, int n_in,
                              void* d_out, int out_size)
{
    const float* s_emb  = (const float*)d_in[0];
    const float* t_emb  = (const float*)d_in[1];
    const float* basis  = (const float*)d_in[2];
    const float* q_W    = (const float*)d_in[3];
    const float* q_b    = (const float*)d_in[4];
    const float* k_W    = (const float*)d_in[5];
    const float* k_b    = (const float*)d_in[6];
    const float* qk_W   = (const float*)d_in[7];
    const float* qk_b   = (const float*)d_in[8];
    const float* bk_W   = (const float*)d_in[9];
    // d_in[10] = bk_b : provably unused (softmax shift invariance)
    const float* bv_W   = (const float*)d_in[11];
    const float* bv_b   = (const float*)d_in[12];
    float* out = (float*)d_out;

    float *p_qk, *p_u, *p_y, *p_A, *p_Bm, *p_c, *p_bkT;
    cudaGetSymbolAddress((void**)&p_qk,  g_qk);
    cudaGetSymbolAddress((void**)&p_u,   g_u);
    cudaGetSymbolAddress((void**)&p_y,   g_y);
    cudaGetSymbolAddress((void**)&p_A,   g_A);
    cudaGetSymbolAddress((void**)&p_Bm,  g_Bm);
    cudaGetSymbolAddress((void**)&p_c,   g_c);
    cudaGetSymbolAddress((void**)&p_bkT, g_bkT);

    const int att_smem = (BB * DHID + BB * SS_LD) * (int)sizeof(float);
    cudaFuncSetAttribute(attention_kernel,
                         cudaFuncAttributeMaxDynamicSharedMemorySize, att_smem);

    // 1) Prep: fused projection matrices + bias + bk_W transpose
    {
        dim3 grid(DHID / BN, DA / BM);
        gemm_nn_kernel<<<grid, 256>>>(p_A,  qk_W,      q_W, nullptr, DA, DHID, DA, 2 * DA);
        gemm_nn_kernel<<<grid, 256>>>(p_Bm, qk_W + DA, k_W, nullptr, DA, DHID, DA, 2 * DA);
        fuse_bias_kernel<<<1, DA>>>(p_c, qk_W, q_b, k_b, qk_b);
        dim3 tg(DHID / 32, DA / 32);
        transpose_kernel<<<tg, dim3(32, 8)>>>(p_bkT, bk_W, DA, DHID);
    }

    // 2) qk = s @ A^T + t @ Bm^T + c       (32768 x 512, K=1024)  [tensor core]
    {
        dim3 grid(DA / 128, MTOT / 128);
        gemm_nt_bf16x3_kernel<<<grid, 256>>>(p_qk, s_emb, p_A, t_emb, p_Bm, p_c,
                                             MTOT, DA, DHID);
    }

    // 3) u = qk @ bk_W = qk @ (bkT)^T      (32768 x 1024, K=512)  [tensor core]
    {
        dim3 grid(DHID / 128, MTOT / 128);
        gemm_nt_bf16x3_kernel<<<grid, 256>>>(p_u, p_qk, p_bkT, nullptr, nullptr, nullptr,
                                             MTOT, DHID, DA);
    }

    // 4) attention: scores -> softmax -> y  (one block per l)
    attention_kernel<<<LL, 256, att_smem>>>(p_u, basis, p_y);

    // 5) z = y @ bv_W^T + bv_b              (32768 x 512, K=1024)  [tensor core]
    {
        dim3 grid(DA / 128, MTOT / 128);
        gemm_nt_bf16x3_kernel<<<grid, 256>>>(out, p_y, bv_W, nullptr, nullptr, bv_b,
                                             MTOT, DA, DHID);
    }
}

// round 5
// speedup vs baseline: 2.2829x; 1.1575x over previous
#include <cuda_runtime.h>
#include <cuda_fp16.h>
#include <math.h>
#include <stdint.h>

// Problem constants
#define DHID 1024
#define DA   512
#define BB   16
#define LL   2048
#define RR   64
#define MTOT (BB*LL)   // 32768

// ---------------------------------------------------------------------------
// Scratch (static device globals; no allocations allowed)
// ---------------------------------------------------------------------------
__device__ __half g_sh [(size_t)MTOT * DHID];  // student hi
__device__ __half g_sl [(size_t)MTOT * DHID];  // student lo
__device__ __half g_th [(size_t)MTOT * DHID];  // teacher hi
__device__ __half g_tl [(size_t)MTOT * DHID];  // teacher lo
__device__ __half g_qh [(size_t)MTOT * DA];    // qk hi
__device__ __half g_ql [(size_t)MTOT * DA];    // qk lo
__device__ float  g_u  [(size_t)MTOT * DHID];  // u (fp32, attention input)
__device__ __half g_yh [(size_t)MTOT * DHID];  // y hi
__device__ __half g_yl [(size_t)MTOT * DHID];  // y lo
__device__ float  g_A  [DA * DHID];            // fused qk_W1 @ q_W (fp32)
__device__ float  g_Bm [DA * DHID];            // fused qk_W2 @ k_W (fp32)
__device__ float  g_c  [DA];                   // fused bias
__device__ float  g_bkT[DHID * DA];            // bk_W transposed (fp32)
__device__ __half g_Ah  [DA * DHID];           // fp16 weights
__device__ __half g_Bmh [DA * DHID];
__device__ __half g_bkTh[DHID * DA];
__device__ __half g_bvh [DA * DHID];

// ---------------------------------------------------------------------------
// mma / ldmatrix helpers (baseline sm_80+ instructions; no 'a' features)
// ---------------------------------------------------------------------------
__device__ __forceinline__ void mma_f16(float* c, const uint32_t* a,
                                        uint32_t b0, uint32_t b1)
{
    asm volatile(
        "mma.sync.aligned.m16n8k16.row.col.f32.f16.f16.f32 "
        "{%0,%1,%2,%3}, {%4,%5,%6,%7}, {%8,%9}, {%0,%1,%2,%3};\n"
        : "+f"(c[0]), "+f"(c[1]), "+f"(c[2]), "+f"(c[3])
        : "r"(a[0]), "r"(a[1]), "r"(a[2]), "r"(a[3]), "r"(b0), "r"(b1));
}

__device__ __forceinline__ void ldm_x4(uint32_t* r, uint32_t addr)
{
    asm volatile(
        "ldmatrix.sync.aligned.m8n8.x4.shared.b16 {%0,%1,%2,%3}, [%4];\n"
        : "=r"(r[0]), "=r"(r[1]), "=r"(r[2]), "=r"(r[3]) : "r"(addr));
}

__device__ __forceinline__ uint32_t smem_u32(const void* p) {
    uint32_t a;
    asm("{ .reg .u64 t; cvta.to.shared.u64 t, %1; cvt.u32.u64 %0, t; }"
        : "=r"(a) : "l"(p));
    return a;
}

#define CP_ASYNC16(dst, src) \
    asm volatile("cp.async.cg.shared.global [%0], [%1], 16;" \
                 :: "r"(dst), "l"(src) : "memory")
#define CP_COMMIT() asm volatile("cp.async.commit_group;" ::: "memory")
#define CP_WAIT1()  asm volatile("cp.async.wait_group 1;" ::: "memory")
#define CP_WAIT0()  asm volatile("cp.async.wait_group 0;" ::: "memory")

// ---------------------------------------------------------------------------
// fp16 2-pass GEMM (NT): C[m,n] = sum_k (Xh+Xl)[m,k]*W[n,k] (2 phases) + bias
// X planes, W: fp16 row-major. Tile 128x128x32; 8 warps of 32x64;
// 3-stage cp.async pipeline; ldmatrix fragments; padded rows (80B) in smem.
// ---------------------------------------------------------------------------
#define ROWB   80                     // bytes per smem row (32 fp16 + 8 pad)
#define PLANE  (128 * ROWB)           // 10240 B
#define STAGE  (3 * PLANE)            // A_hi, A_lo, B = 30720 B
#define NSTAGE 3
#define GEMM_SMEM (NSTAGE * STAGE)    // 92160 B

struct GArgs {
    const __half *Xh1, *Xl1, *W1;
    const __half *Xh2, *Xl2, *W2;
    int K1, K2;
};

__device__ __forceinline__ void load_stage(
    uint32_t sb, const __half* Xh, const __half* Xl, const __half* Wp,
    int ld, int bm, int bn, int k0, int t)
{
    #pragma unroll
    for (int o = 0; o < 6; ++o) {
        int idx   = t + o * 256;          // 0..1535
        int plane = idx >> 9;             // 0: A_hi, 1: A_lo, 2: B
        int p     = idx & 511;
        int row   = p >> 2;
        int grp   = p & 3;
        uint32_t dst = sb + plane * PLANE + row * ROWB + grp * 16;
        const __half* src;
        if (plane == 0)      src = Xh + (size_t)(bm + row) * ld + k0 + grp * 8;
        else if (plane == 1) src = Xl + (size_t)(bm + row) * ld + k0 + grp * 8;
        else                 src = Wp + (size_t)(bn + row) * ld + k0 + grp * 8;
        CP_ASYNC16(dst, src);
    }
}

__global__ void __launch_bounds__(256, 2) gemm_h2_nt(
    GArgs ga,
    const float* __restrict__ bias,
    float* __restrict__ Cf,               // fp32 out (nullable)
    __half* __restrict__ Ch,              // fp16 hi out (nullable)
    __half* __restrict__ Cl,              // fp16 lo out
    int M, int N)
{
    extern __shared__ __align__(16) char smraw[];
    const uint32_t sm0 = smem_u32(smraw);

    const int t    = threadIdx.x;
    const int warp = t >> 5;
    const int lane = t & 31;
    const int bm   = blockIdx.y * 128;
    const int bn   = blockIdx.x * 128;
    const int mw   = (warp & 3) * 32;
    const int nw   = (warp >> 2) * 64;
    const uint32_t laneoff = (lane & 15) * ROWB + (lane >> 4) * 16;

    const int nc1 = ga.K1 / 32;
    const int nch = ga.Xh2 ? nc1 + ga.K2 / 32 : nc1;

    float acc[2][8][4];
    #pragma unroll
    for (int i = 0; i < 2; ++i)
        #pragma unroll
        for (int j = 0; j < 8; ++j)
            #pragma unroll
            for (int e = 0; e < 4; ++e) acc[i][j][e] = 0.f;

    // Prologue: stages 0, 1
    #pragma unroll
    for (int c = 0; c < 2; ++c) {
        if (c < nch) {
            if (c < nc1)
                load_stage(sm0 + c * STAGE, ga.Xh1, ga.Xl1, ga.W1, ga.K1,
                           bm, bn, c * 32, t);
            else
                load_stage(sm0 + c * STAGE, ga.Xh2, ga.Xl2, ga.W2, ga.K2,
                           bm, bn, (c - nc1) * 32, t);
            CP_COMMIT();
        }
    }

    for (int c = 0; c < nch; ++c) {
        if (c + 2 <= nch) CP_WAIT1(); else CP_WAIT0();
        __syncthreads();

        const uint32_t sb = sm0 + (c % NSTAGE) * STAGE;
        #pragma unroll
        for (int ks = 0; ks < 2; ++ks) {
            const uint32_t kb = ks * 32;   // 16 halves = 32 bytes
            uint32_t ah0[4], ah1[4], al0[4], al1[4], bb[4][4];
            const uint32_t aA = sb + mw * ROWB + laneoff + kb;
            ldm_x4(ah0, aA);
            ldm_x4(ah1, aA + 16 * ROWB);
            ldm_x4(al0, aA + PLANE);
            ldm_x4(al1, aA + PLANE + 16 * ROWB);
            const uint32_t bA = sb + 2 * PLANE + nw * ROWB + laneoff + kb;
            #pragma unroll
            for (int j = 0; j < 4; ++j) ldm_x4(bb[j], bA + j * 16 * ROWB);

            #pragma unroll
            for (int i = 0; i < 2; ++i) {
                const uint32_t* ah = i ? ah1 : ah0;
                const uint32_t* al = i ? al1 : al0;
                #pragma unroll
                for (int j8 = 0; j8 < 8; ++j8) {
                    uint32_t b0 = bb[j8 >> 1][j8 & 1];
                    uint32_t b1 = bb[j8 >> 1][(j8 & 1) + 2];
                    mma_f16(acc[i][j8], ah, b0, b1);
                    mma_f16(acc[i][j8], al, b0, b1);
                }
            }
        }
        __syncthreads();

        if (c + 2 < nch) {
            const int cn = c + 2;
            const uint32_t db = sm0 + (cn % NSTAGE) * STAGE;
            if (cn < nc1)
                load_stage(db, ga.Xh1, ga.Xl1, ga.W1, ga.K1, bm, bn, cn * 32, t);
            else
                load_stage(db, ga.Xh2, ga.Xl2, ga.W2, ga.K2, bm, bn,
                           (cn - nc1) * 32, t);
            CP_COMMIT();
        }
    }

    // Epilogue
    const int g = lane >> 2;
    const int q = lane & 3;
    #pragma unroll
    for (int i = 0; i < 2; ++i) {
        #pragma unroll
        for (int j8 = 0; j8 < 8; ++j8) {
            const int r0  = bm + mw + 16 * i + g;
            const int col = bn + nw + 8 * j8 + 2 * q;
            const float b0v = bias ? bias[col]     : 0.f;
            const float b1v = bias ? bias[col + 1] : 0.f;
            float v00 = acc[i][j8][0] + b0v, v01 = acc[i][j8][1] + b1v;
            float v10 = acc[i][j8][2] + b0v, v11 = acc[i][j8][3] + b1v;
            if (Cf) {
                *(float2*)&Cf[(size_t)r0 * N + col]       = make_float2(v00, v01);
                *(float2*)&Cf[(size_t)(r0 + 8) * N + col] = make_float2(v10, v11);
            } else {
                __half h00 = __float2half_rn(v00), h01 = __float2half_rn(v01);
                __half h10 = __float2half_rn(v10), h11 = __float2half_rn(v11);
                __half l00 = __float2half_rn(v00 - __half2float(h00));
                __half l01 = __float2half_rn(v01 - __half2float(h01));
                __half l10 = __float2half_rn(v10 - __half2float(h10));
                __half l11 = __float2half_rn(v11 - __half2float(h11));
                *(__half2*)&Ch[(size_t)r0 * N + col]       = __halves2half2(h00, h01);
                *(__half2*)&Ch[(size_t)(r0 + 8) * N + col] = __halves2half2(h10, h11);
                *(__half2*)&Cl[(size_t)r0 * N + col]       = __halves2half2(l00, l01);
                *(__half2*)&Cl[(size_t)(r0 + 8) * N + col] = __halves2half2(l10, l11);
            }
        }
    }
}

// ---------------------------------------------------------------------------
// Converters
// ---------------------------------------------------------------------------
__global__ void split32to16(__half* __restrict__ h, __half* __restrict__ l,
                            const float* __restrict__ s, int n)
{
    int i = (blockIdx.x * blockDim.x + threadIdx.x) * 4;
    if (i >= n) return;
    float4 v = *(const float4*)&s[i];
    __half h0 = __float2half_rn(v.x), h1 = __float2half_rn(v.y);
    __half h2 = __float2half_rn(v.z), h3 = __float2half_rn(v.w);
    __half l0 = __float2half_rn(v.x - __half2float(h0));
    __half l1 = __float2half_rn(v.y - __half2float(h1));
    __half l2 = __float2half_rn(v.z - __half2float(h2));
    __half l3 = __float2half_rn(v.w - __half2float(h3));
    *(__half2*)&h[i]     = __halves2half2(h0, h1);
    *(__half2*)&h[i + 2] = __halves2half2(h2, h3);
    *(__half2*)&l[i]     = __halves2half2(l0, l1);
    *(__half2*)&l[i + 2] = __halves2half2(l2, l3);
}

__global__ void cvt32to16(__half* __restrict__ h, const float* __restrict__ s, int n)
{
    int i = (blockIdx.x * blockDim.x + threadIdx.x) * 4;
    if (i >= n) return;
    float4 v = *(const float4*)&s[i];
    *(__half2*)&h[i]     = __floats2half2_rn(v.x, v.y);
    *(__half2*)&h[i + 2] = __floats2half2_rn(v.z, v.w);
}

// ---------------------------------------------------------------------------
// Transpose (fp32), once for bk_W
// ---------------------------------------------------------------------------
__global__ void transpose_kernel(float* __restrict__ out, const float* __restrict__ in,
                                 int Rrows, int Ccols)
{
    __shared__ float tile[32][33];
    int x = blockIdx.x * 32 + threadIdx.x;
    int y = blockIdx.y * 32 + threadIdx.y;
    #pragma unroll
    for (int i = 0; i < 4; ++i)
        tile[threadIdx.y + 8 * i][threadIdx.x] = in[(size_t)(y + 8 * i) * Ccols + x];
    __syncthreads();
    x = blockIdx.y * 32 + threadIdx.x;
    y = blockIdx.x * 32 + threadIdx.y;
    #pragma unroll
    for (int i = 0; i < 4; ++i)
        out[(size_t)(y + 8 * i) * Rrows + x] = tile[threadIdx.x][threadIdx.y + 8 * i];
}

// ---------------------------------------------------------------------------
// fp32 SIMT GEMM (NN) — small prep GEMMs only (512x1024x512).
// ---------------------------------------------------------------------------
#define BM 128
#define BN 128
#define BK 16

__global__ void __launch_bounds__(256, 2) gemm_nn_kernel(
    float* __restrict__ C,
    const float* __restrict__ X, const float* __restrict__ W,
    const float* __restrict__ bias,
    int M, int N, int K, int ldx)
{
    __shared__ float As[BK][BM];
    __shared__ float Bs[BK][BN];
    const int t  = threadIdx.x;
    const int bm = blockIdx.y * BM;
    const int bn = blockIdx.x * BN;

    float acc[8][8];
    #pragma unroll
    for (int i = 0; i < 8; ++i)
        #pragma unroll
        for (int j = 0; j < 8; ++j) acc[i][j] = 0.f;

    const int lrow = t >> 2;
    const int lc4  = (t & 3) * 4;
    const int wk   = t >> 5;
    const int wn4  = (t & 31) * 4;

    for (int k0 = 0; k0 < K; k0 += BK) {
        #pragma unroll
        for (int h = 0; h < 2; ++h) {
            int row = lrow + h * 64;
            float4 v = *(const float4*)&X[(size_t)(bm + row) * ldx + k0 + lc4];
            As[lc4 + 0][row] = v.x;
            As[lc4 + 1][row] = v.y;
            As[lc4 + 2][row] = v.z;
            As[lc4 + 3][row] = v.w;
            int k = wk + h * 8;
            float4 w = *(const float4*)&W[(size_t)(k0 + k) * N + bn + wn4];
            *(float4*)&Bs[k][wn4] = w;
        }
        __syncthreads();
        const int m8 = (t >> 4) * 8;
        const int n8 = (t & 15) * 8;
        #pragma unroll
        for (int kk = 0; kk < BK; ++kk) {
            float a[8], b[8];
            *(float4*)&a[0] = *(const float4*)&As[kk][m8];
            *(float4*)&a[4] = *(const float4*)&As[kk][m8 + 4];
            *(float4*)&b[0] = *(const float4*)&Bs[kk][n8];
            *(float4*)&b[4] = *(const float4*)&Bs[kk][n8 + 4];
            #pragma unroll
            for (int i = 0; i < 8; ++i)
                #pragma unroll
                for (int j = 0; j < 8; ++j)
                    acc[i][j] += a[i] * b[j];
        }
        __syncthreads();
    }

    const int m0 = bm + (t >> 4) * 8;
    const int n0 = bn + (t & 15) * 8;
    #pragma unroll
    for (int i = 0; i < 8; ++i) {
        float4 o0, o1;
        o0.x = acc[i][0]; o0.y = acc[i][1]; o0.z = acc[i][2]; o0.w = acc[i][3];
        o1.x = acc[i][4]; o1.y = acc[i][5]; o1.z = acc[i][6]; o1.w = acc[i][7];
        *(float4*)&C[(size_t)(m0 + i) * N + n0]     = o0;
        *(float4*)&C[(size_t)(m0 + i) * N + n0 + 4] = o1;
    }
}

// ---------------------------------------------------------------------------
// Fused bias: c[i] = sum_j qk_W[i,j]*q_b[j] + qk_W[i,512+j]*k_b[j] + qk_b[i]
// ---------------------------------------------------------------------------
__global__ void fuse_bias_kernel(float* __restrict__ c,
                                 const float* __restrict__ qk_W,
                                 const float* __restrict__ q_b,
                                 const float* __restrict__ k_b,
                                 const float* __restrict__ qk_b)
{
    int i = blockIdx.x * blockDim.x + threadIdx.x;
    if (i >= DA) return;
    float s = qk_b[i];
    const float* row = qk_W + (size_t)i * (2 * DA);
    for (int j = 0; j < DA; ++j)
        s += row[j] * q_b[j] + row[DA + j] * k_b[j];
    c[i] = s;
}

// ---------------------------------------------------------------------------
// Attention: one block per l. scores -> softmax -> y (emitted as fp16 hi/lo)
// ---------------------------------------------------------------------------
#define SS_LD 65

__global__ void __launch_bounds__(256) attention_kernel(
    const float* __restrict__ u,      // (B*L, 1024)
    const float* __restrict__ basis,  // (L, R, 1024)
    __half* __restrict__ yh, __half* __restrict__ yl)
{
    extern __shared__ float smf[];
    float* u_s = smf;                      // 16 * 1024
    float* s_s = smf + BB * DHID;          // 16 * SS_LD

    const int l    = blockIdx.x;
    const int t    = threadIdx.x;
    const int warp = t >> 5;
    const int lane = t & 31;
    const float scale = 0.044194173824159216f;  // 1/sqrt(512)

    for (int idx = t; idx < BB * DHID / 4; idx += 256) {
        int b  = idx >> 8;
        int d4 = idx & 255;
        *(float4*)&u_s[b * DHID + d4 * 4] =
            *(const float4*)&u[((size_t)b * LL + l) * DHID + d4 * 4];
    }
    __syncthreads();

    const float* basl = basis + (size_t)l * RR * DHID;

    for (int rr = 0; rr < 8; ++rr) {
        int r = warp * 8 + rr;
        const float* brow = basl + (size_t)r * DHID;
        float bas[32];
        #pragma unroll
        for (int i = 0; i < 32; ++i) bas[i] = brow[lane + 32 * i];
        #pragma unroll
        for (int b = 0; b < BB; ++b) {
            float p = 0.f;
            const float* ur = &u_s[b * DHID];
            #pragma unroll
            for (int i = 0; i < 32; ++i) p += bas[i] * ur[lane + 32 * i];
            #pragma unroll
            for (int o = 16; o; o >>= 1) p += __shfl_xor_sync(0xffffffffu, p, o);
            if (lane == 0) s_s[b * SS_LD + r] = p * scale;
        }
    }
    __syncthreads();

    {
        int b0 = warp * 2;
        #pragma unroll
        for (int bi = 0; bi < 2; ++bi) {
            int b = b0 + bi;
            float v0 = s_s[b * SS_LD + lane];
            float v1 = s_s[b * SS_LD + lane + 32];
            float mx = fmaxf(v0, v1);
            #pragma unroll
            for (int o = 16; o; o >>= 1) mx = fmaxf(mx, __shfl_xor_sync(0xffffffffu, mx, o));
            float e0 = __expf(v0 - mx);
            float e1 = __expf(v1 - mx);
            float sum = e0 + e1;
            #pragma unroll
            for (int o = 16; o; o >>= 1) sum += __shfl_xor_sync(0xffffffffu, sum, o);
            float inv = 1.f / sum;
            s_s[b * SS_LD + lane]      = e0 * inv;
            s_s[b * SS_LD + lane + 32] = e1 * inv;
        }
    }
    __syncthreads();

    for (int i = 0; i < 4; ++i) {
        int d = i * 256 + t;
        float acc[BB];
        #pragma unroll
        for (int b = 0; b < BB; ++b) acc[b] = 0.f;
        #pragma unroll 4
        for (int r = 0; r < RR; ++r) {
            float bv = basl[(size_t)r * DHID + d];
            #pragma unroll
            for (int b = 0; b < BB; ++b)
                acc[b] += s_s[b * SS_LD + r] * bv;
        }
        #pragma unroll
        for (int b = 0; b < BB; ++b) {
            size_t off = ((size_t)b * LL + l) * DHID + d;
            __half h = __float2half_rn(acc[b]);
            yh[off] = h;
            yl[off] = __float2half_rn(acc[b] - __half2float(h));
        }
    }
}

// ---------------------------------------------------------------------------
// Launch
// ---------------------------------------------------------------------------
extern "C" void kernel_launch(void* const* d_in, const int* in_sizes, int n_in,
                              void* d_out, int out_size)
{
    const float* s_emb  = (const float*)d_in[0];
    const float* t_emb  = (const float*)d_in[1];
    const float* basis  = (const float*)d_in[2];
    const float* q_W    = (const float*)d_in[3];
    const float* q_b    = (const float*)d_in[4];
    const float* k_W    = (const float*)d_in[5];
    const float* k_b    = (const float*)d_in[6];
    const float* qk_W   = (const float*)d_in[7];
    const float* qk_b   = (const float*)d_in[8];
    const float* bk_W   = (const float*)d_in[9];
    // d_in[10] = bk_b : provably unused (softmax shift invariance)
    const float* bv_W   = (const float*)d_in[11];
    const float* bv_b   = (const float*)d_in[12];
    float* out = (float*)d_out;

    float  *p_u, *p_A, *p_Bm, *p_c, *p_bkT;
    __half *p_sh, *p_sl, *p_th, *p_tl, *p_qh, *p_ql, *p_yh, *p_yl;
    __half *p_Ah, *p_Bmh, *p_bkTh, *p_bvh;
    cudaGetSymbolAddress((void**)&p_u,    g_u);
    cudaGetSymbolAddress((void**)&p_A,    g_A);
    cudaGetSymbolAddress((void**)&p_Bm,   g_Bm);
    cudaGetSymbolAddress((void**)&p_c,    g_c);
    cudaGetSymbolAddress((void**)&p_bkT,  g_bkT);
    cudaGetSymbolAddress((void**)&p_sh,   g_sh);
    cudaGetSymbolAddress((void**)&p_sl,   g_sl);
    cudaGetSymbolAddress((void**)&p_th,   g_th);
    cudaGetSymbolAddress((void**)&p_tl,   g_tl);
    cudaGetSymbolAddress((void**)&p_qh,   g_qh);
    cudaGetSymbolAddress((void**)&p_ql,   g_ql);
    cudaGetSymbolAddress((void**)&p_yh,   g_yh);
    cudaGetSymbolAddress((void**)&p_yl,   g_yl);
    cudaGetSymbolAddress((void**)&p_Ah,   g_Ah);
    cudaGetSymbolAddress((void**)&p_Bmh,  g_Bmh);
    cudaGetSymbolAddress((void**)&p_bkTh, g_bkTh);
    cudaGetSymbolAddress((void**)&p_bvh,  g_bvh);

    const int att_smem = (BB * DHID + BB * SS_LD) * (int)sizeof(float);
    cudaFuncSetAttribute(attention_kernel,
                         cudaFuncAttributeMaxDynamicSharedMemorySize, att_smem);
    cudaFuncSetAttribute(gemm_h2_nt,
                         cudaFuncAttributeMaxDynamicSharedMemorySize, GEMM_SMEM);

    // 1) Prep: fused projection matrices + bias + bk_W transpose (fp32)
    {
        dim3 grid(DHID / BN, DA / BM);
        gemm_nn_kernel<<<grid, 256>>>(p_A,  qk_W,      q_W, nullptr, DA, DHID, DA, 2 * DA);
        gemm_nn_kernel<<<grid, 256>>>(p_Bm, qk_W + DA, k_W, nullptr, DA, DHID, DA, 2 * DA);
        fuse_bias_kernel<<<1, DA>>>(p_c, qk_W, q_b, k_b, qk_b);
        dim3 tg(DHID / 32, DA / 32);
        transpose_kernel<<<tg, dim3(32, 8)>>>(p_bkT, bk_W, DA, DHID);
    }

    // 2) Converts: activations -> fp16 hi/lo; weights -> fp16
    {
        const int ne = MTOT * DHID;                   // 33.5M
        split32to16<<<ne / 4 / 256, 256>>>(p_sh, p_sl, s_emb, ne);
        split32to16<<<ne / 4 / 256, 256>>>(p_th, p_tl, t_emb, ne);
        const int nw = DA * DHID;                     // 524288
        cvt32to16<<<nw / 4 / 256, 256>>>(p_Ah,   p_A,   nw);
        cvt32to16<<<nw / 4 / 256, 256>>>(p_Bmh,  p_Bm,  nw);
        cvt32to16<<<nw / 4 / 256, 256>>>(p_bkTh, p_bkT, nw);
        cvt32to16<<<nw / 4 / 256, 256>>>(p_bvh,  bv_W,  nw);
    }

    // 3) qk = s@A^T + t@Bm^T + c  (32768x512, K=1024x2)  -> fp16 hi/lo
    {
        GArgs ga = { p_sh, p_sl, p_Ah, p_th, p_tl, p_Bmh, DHID, DHID };
        dim3 grid(DA / 128, MTOT / 128);
        gemm_h2_nt<<<grid, 256, GEMM_SMEM>>>(ga, p_c, nullptr, p_qh, p_ql,
                                             MTOT, DA);
    }

    // 4) u = qk @ bkT^T  (32768x1024, K=512)  -> fp32
    {
        GArgs ga = { p_qh, p_ql, p_bkTh, nullptr, nullptr, nullptr, DA, 0 };
        dim3 grid(DHID / 128, MTOT / 128);
        gemm_h2_nt<<<grid, 256, GEMM_SMEM>>>(ga, nullptr, p_u, nullptr, nullptr,
                                             MTOT, DHID);
    }

    // 5) attention: scores -> softmax -> y (fp16 hi/lo)
    attention_kernel<<<LL, 256, att_smem>>>(p_u, basis, p_yh, p_yl);

    // 6) z = y @ bv_W^T + bv_b  (32768x512, K=1024)  -> fp32 out
    {
        GArgs ga = { p_yh, p_yl, p_bvh, nullptr, nullptr, nullptr, DHID, 0 };
        dim3 grid(DA / 128, MTOT / 128);
        gemm_h2_nt<<<grid, 256, GEMM_SMEM>>>(ga, bv_b, out, nullptr, nullptr,
                                             MTOT, DA);
    }
}

// round 6
// speedup vs baseline: 2.6413x; 1.1570x over previous
#include <cuda_runtime.h>
#include <cuda_fp16.h>
#include <math.h>
#include <stdint.h>

// Problem constants
#define DHID 1024
#define DA   512
#define BB   16
#define LL   2048
#define RR   64
#define MTOT (BB*LL)   // 32768

// ---------------------------------------------------------------------------
// Scratch (static device globals; no allocations allowed)
// ---------------------------------------------------------------------------
__device__ __half g_sh [(size_t)MTOT * DHID];  // student fp16
__device__ __half g_th [(size_t)MTOT * DHID];  // teacher fp16
__device__ __half g_qh [(size_t)MTOT * DA];    // qk fp16
__device__ float  g_u  [(size_t)MTOT * DHID];  // u (fp32, attention input)
__device__ __half g_yh [(size_t)MTOT * DHID];  // y hi
__device__ __half g_yl [(size_t)MTOT * DHID];  // y lo
__device__ float  g_A  [DA * DHID];            // fused qk_W1 @ q_W (fp32)
__device__ float  g_Bm [DA * DHID];            // fused qk_W2 @ k_W (fp32)
__device__ float  g_c  [DA];                   // fused bias
__device__ float  g_bkT[DHID * DA];            // bk_W transposed (fp32)
__device__ __half g_Ah  [DA * DHID];           // fp16 weights
__device__ __half g_Bmh [DA * DHID];
__device__ __half g_bkTh[DHID * DA];
__device__ __half g_bvh [DA * DHID];

// ---------------------------------------------------------------------------
// mma / ldmatrix helpers (baseline sm_80+ instructions; no 'a' features)
// ---------------------------------------------------------------------------
__device__ __forceinline__ void mma_f16(float* c, const uint32_t* a,
                                        uint32_t b0, uint32_t b1)
{
    asm volatile(
        "mma.sync.aligned.m16n8k16.row.col.f32.f16.f16.f32 "
        "{%0,%1,%2,%3}, {%4,%5,%6,%7}, {%8,%9}, {%0,%1,%2,%3};\n"
        : "+f"(c[0]), "+f"(c[1]), "+f"(c[2]), "+f"(c[3])
        : "r"(a[0]), "r"(a[1]), "r"(a[2]), "r"(a[3]), "r"(b0), "r"(b1));
}

__device__ __forceinline__ void ldm_x4(uint32_t* r, uint32_t addr)
{
    asm volatile(
        "ldmatrix.sync.aligned.m8n8.x4.shared.b16 {%0,%1,%2,%3}, [%4];\n"
        : "=r"(r[0]), "=r"(r[1]), "=r"(r[2]), "=r"(r[3]) : "r"(addr));
}

__device__ __forceinline__ uint32_t smem_u32(const void* p) {
    uint32_t a;
    asm("{ .reg .u64 t; cvta.to.shared.u64 t, %1; cvt.u32.u64 %0, t; }"
        : "=r"(a) : "l"(p));
    return a;
}

#define CP_ASYNC16(dst, src) \
    asm volatile("cp.async.cg.shared.global [%0], [%1], 16;" \
                 :: "r"(dst), "l"(src) : "memory")
#define CP_COMMIT() asm volatile("cp.async.commit_group;" ::: "memory")
#define CP_WAIT1()  asm volatile("cp.async.wait_group 1;" ::: "memory")
#define CP_WAIT0()  asm volatile("cp.async.wait_group 0;" ::: "memory")

// ---------------------------------------------------------------------------
// fp16 GEMM (NT), templated on LO (2-pass hi/lo activation split or 1-pass):
//   C[m,n] = sum_k (Xh[+Xl])[m,k]*W[n,k] (over 1 or 2 input phases) + bias[n]
// Tile 128x128x32; 8 warps of 32x64; 3-stage cp.async pipeline; ldmatrix;
// padded smem rows (80 B).
// ---------------------------------------------------------------------------
#define ROWB   80                     // bytes per smem row (32 fp16 + 8 pad)
#define PLANE  (128 * ROWB)           // 10240 B
#define NSTAGE 3
#define SMEM_LO (NSTAGE * 3 * PLANE)  // 92160 B (A_hi, A_lo, B)
#define SMEM_HI (NSTAGE * 2 * PLANE)  // 61440 B (A_hi, B)

struct GArgs {
    const __half *Xh1, *Xl1, *W1;
    const __half *Xh2, *Xl2, *W2;
    int K1, K2;
};

template <bool LO>
__device__ __forceinline__ void load_stage(
    uint32_t sb, const __half* Xh, const __half* Xl, const __half* Wp,
    int ld, int bm, int bn, int k0, int t)
{
    const int NPL = LO ? 3 : 2;
    #pragma unroll
    for (int o = 0; o < 2 * NPL; ++o) {
        int idx   = t + o * 256;
        int plane = idx >> 9;
        int p     = idx & 511;
        int row   = p >> 2;
        int grp   = p & 3;
        uint32_t dst = sb + plane * PLANE + row * ROWB + grp * 16;
        const __half* src;
        if (LO) {
            if (plane == 0)      src = Xh + (size_t)(bm + row) * ld + k0 + grp * 8;
            else if (plane == 1) src = Xl + (size_t)(bm + row) * ld + k0 + grp * 8;
            else                 src = Wp + (size_t)(bn + row) * ld + k0 + grp * 8;
        } else {
            if (plane == 0)      src = Xh + (size_t)(bm + row) * ld + k0 + grp * 8;
            else                 src = Wp + (size_t)(bn + row) * ld + k0 + grp * 8;
        }
        CP_ASYNC16(dst, src);
    }
}

template <bool LO>
__global__ void __launch_bounds__(256, 2) gemm_h_nt(
    GArgs ga,
    const float* __restrict__ bias,
    float* __restrict__ Cf,               // fp32 out (nullable)
    __half* __restrict__ Ch,              // fp16 hi out (if Cf null)
    __half* __restrict__ Cl,              // fp16 lo out (nullable)
    int M, int N)
{
    extern __shared__ __align__(16) char smraw[];
    const uint32_t sm0    = smem_u32(smraw);
    const uint32_t STAGEB = (LO ? 3 : 2) * PLANE;
    const uint32_t BPOFF  = (LO ? 2 : 1) * PLANE;

    const int t    = threadIdx.x;
    const int warp = t >> 5;
    const int lane = t & 31;
    const int bm   = blockIdx.y * 128;
    const int bn   = blockIdx.x * 128;
    const int mw   = (warp & 3) * 32;
    const int nw   = (warp >> 2) * 64;
    const uint32_t laneoff = (lane & 15) * ROWB + (lane >> 4) * 16;

    const int nc1 = ga.K1 / 32;
    const int nch = ga.Xh2 ? nc1 + ga.K2 / 32 : nc1;

    float acc[2][8][4];
    #pragma unroll
    for (int i = 0; i < 2; ++i)
        #pragma unroll
        for (int j = 0; j < 8; ++j)
            #pragma unroll
            for (int e = 0; e < 4; ++e) acc[i][j][e] = 0.f;

    // Prologue: stages 0, 1
    #pragma unroll
    for (int c = 0; c < 2; ++c) {
        if (c < nch) {
            if (c < nc1)
                load_stage<LO>(sm0 + c * STAGEB, ga.Xh1, ga.Xl1, ga.W1, ga.K1,
                               bm, bn, c * 32, t);
            else
                load_stage<LO>(sm0 + c * STAGEB, ga.Xh2, ga.Xl2, ga.W2, ga.K2,
                               bm, bn, (c - nc1) * 32, t);
            CP_COMMIT();
        }
    }

    for (int c = 0; c < nch; ++c) {
        if (c + 2 <= nch) CP_WAIT1(); else CP_WAIT0();
        __syncthreads();

        const uint32_t sb = sm0 + (c % NSTAGE) * STAGEB;
        #pragma unroll
        for (int ks = 0; ks < 2; ++ks) {
            const uint32_t kb = ks * 32;   // 16 halves = 32 bytes
            uint32_t ah0[4], ah1[4], al0[4], al1[4], bb[4][4];
            const uint32_t aA = sb + mw * ROWB + laneoff + kb;
            ldm_x4(ah0, aA);
            ldm_x4(ah1, aA + 16 * ROWB);
            if (LO) {
                ldm_x4(al0, aA + PLANE);
                ldm_x4(al1, aA + PLANE + 16 * ROWB);
            }
            const uint32_t bA = sb + BPOFF + nw * ROWB + laneoff + kb;
            #pragma unroll
            for (int j = 0; j < 4; ++j) ldm_x4(bb[j], bA + j * 16 * ROWB);

            #pragma unroll
            for (int i = 0; i < 2; ++i) {
                const uint32_t* ah = i ? ah1 : ah0;
                const uint32_t* al = i ? al1 : al0;
                #pragma unroll
                for (int j8 = 0; j8 < 8; ++j8) {
                    uint32_t b0 = bb[j8 >> 1][j8 & 1];
                    uint32_t b1 = bb[j8 >> 1][(j8 & 1) + 2];
                    mma_f16(acc[i][j8], ah, b0, b1);
                    if (LO) mma_f16(acc[i][j8], al, b0, b1);
                }
            }
        }
        __syncthreads();

        if (c + 2 < nch) {
            const int cn = c + 2;
            const uint32_t db = sm0 + (cn % NSTAGE) * STAGEB;
            if (cn < nc1)
                load_stage<LO>(db, ga.Xh1, ga.Xl1, ga.W1, ga.K1, bm, bn,
                               cn * 32, t);
            else
                load_stage<LO>(db, ga.Xh2, ga.Xl2, ga.W2, ga.K2, bm, bn,
                               (cn - nc1) * 32, t);
            CP_COMMIT();
        }
    }

    // Epilogue
    const int g = lane >> 2;
    const int q = lane & 3;
    #pragma unroll
    for (int i = 0; i < 2; ++i) {
        #pragma unroll
        for (int j8 = 0; j8 < 8; ++j8) {
            const int r0  = bm + mw + 16 * i + g;
            const int col = bn + nw + 8 * j8 + 2 * q;
            const float b0v = bias ? bias[col]     : 0.f;
            const float b1v = bias ? bias[col + 1] : 0.f;
            float v00 = acc[i][j8][0] + b0v, v01 = acc[i][j8][1] + b1v;
            float v10 = acc[i][j8][2] + b0v, v11 = acc[i][j8][3] + b1v;
            if (Cf) {
                *(float2*)&Cf[(size_t)r0 * N + col]       = make_float2(v00, v01);
                *(float2*)&Cf[(size_t)(r0 + 8) * N + col] = make_float2(v10, v11);
            } else {
                __half h00 = __float2half_rn(v00), h01 = __float2half_rn(v01);
                __half h10 = __float2half_rn(v10), h11 = __float2half_rn(v11);
                *(__half2*)&Ch[(size_t)r0 * N + col]       = __halves2half2(h00, h01);
                *(__half2*)&Ch[(size_t)(r0 + 8) * N + col] = __halves2half2(h10, h11);
                if (Cl) {
                    __half l00 = __float2half_rn(v00 - __half2float(h00));
                    __half l01 = __float2half_rn(v01 - __half2float(h01));
                    __half l10 = __float2half_rn(v10 - __half2float(h10));
                    __half l11 = __float2half_rn(v11 - __half2float(h11));
                    *(__half2*)&Cl[(size_t)r0 * N + col]       = __halves2half2(l00, l01);
                    *(__half2*)&Cl[(size_t)(r0 + 8) * N + col] = __halves2half2(l10, l11);
                }
            }
        }
    }
}

// ---------------------------------------------------------------------------
// Converter: fp32 -> fp16 (round-to-nearest)
// ---------------------------------------------------------------------------
__global__ void cvt32to16(__half* __restrict__ h, const float* __restrict__ s, int n)
{
    int i = (blockIdx.x * blockDim.x + threadIdx.x) * 4;
    if (i >= n) return;
    float4 v = *(const float4*)&s[i];
    *(__half2*)&h[i]     = __floats2half2_rn(v.x, v.y);
    *(__half2*)&h[i + 2] = __floats2half2_rn(v.z, v.w);
}

// ---------------------------------------------------------------------------
// Transpose (fp32), once for bk_W
// ---------------------------------------------------------------------------
__global__ void transpose_kernel(float* __restrict__ out, const float* __restrict__ in,
                                 int Rrows, int Ccols)
{
    __shared__ float tile[32][33];
    int x = blockIdx.x * 32 + threadIdx.x;
    int y = blockIdx.y * 32 + threadIdx.y;
    #pragma unroll
    for (int i = 0; i < 4; ++i)
        tile[threadIdx.y + 8 * i][threadIdx.x] = in[(size_t)(y + 8 * i) * Ccols + x];
    __syncthreads();
    x = blockIdx.y * 32 + threadIdx.x;
    y = blockIdx.x * 32 + threadIdx.y;
    #pragma unroll
    for (int i = 0; i < 4; ++i)
        out[(size_t)(y + 8 * i) * Rrows + x] = tile[threadIdx.x][threadIdx.y + 8 * i];
}

// ---------------------------------------------------------------------------
// fp32 SIMT GEMM (NN) — small prep GEMMs only (512x1024x512).
// ---------------------------------------------------------------------------
#define BM 128
#define BN 128
#define BK 16

__global__ void __launch_bounds__(256, 2) gemm_nn_kernel(
    float* __restrict__ C,
    const float* __restrict__ X, const float* __restrict__ W,
    int M, int N, int K, int ldx)
{
    __shared__ float As[BK][BM];
    __shared__ float Bs[BK][BN];
    const int t  = threadIdx.x;
    const int bm = blockIdx.y * BM;
    const int bn = blockIdx.x * BN;

    float acc[8][8];
    #pragma unroll
    for (int i = 0; i < 8; ++i)
        #pragma unroll
        for (int j = 0; j < 8; ++j) acc[i][j] = 0.f;

    const int lrow = t >> 2;
    const int lc4  = (t & 3) * 4;
    const int wk   = t >> 5;
    const int wn4  = (t & 31) * 4;

    for (int k0 = 0; k0 < K; k0 += BK) {
        #pragma unroll
        for (int h = 0; h < 2; ++h) {
            int row = lrow + h * 64;
            float4 v = *(const float4*)&X[(size_t)(bm + row) * ldx + k0 + lc4];
            As[lc4 + 0][row] = v.x;
            As[lc4 + 1][row] = v.y;
            As[lc4 + 2][row] = v.z;
            As[lc4 + 3][row] = v.w;
            int k = wk + h * 8;
            float4 w = *(const float4*)&W[(size_t)(k0 + k) * N + bn + wn4];
            *(float4*)&Bs[k][wn4] = w;
        }
        __syncthreads();
        const int m8 = (t >> 4) * 8;
        const int n8 = (t & 15) * 8;
        #pragma unroll
        for (int kk = 0; kk < BK; ++kk) {
            float a[8], b[8];
            *(float4*)&a[0] = *(const float4*)&As[kk][m8];
            *(float4*)&a[4] = *(const float4*)&As[kk][m8 + 4];
            *(float4*)&b[0] = *(const float4*)&Bs[kk][n8];
            *(float4*)&b[4] = *(const float4*)&Bs[kk][n8 + 4];
            #pragma unroll
            for (int i = 0; i < 8; ++i)
                #pragma unroll
                for (int j = 0; j < 8; ++j)
                    acc[i][j] += a[i] * b[j];
        }
        __syncthreads();
    }

    const int m0 = bm + (t >> 4) * 8;
    const int n0 = bn + (t & 15) * 8;
    #pragma unroll
    for (int i = 0; i < 8; ++i) {
        float4 o0, o1;
        o0.x = acc[i][0]; o0.y = acc[i][1]; o0.z = acc[i][2]; o0.w = acc[i][3];
        o1.x = acc[i][4]; o1.y = acc[i][5]; o1.z = acc[i][6]; o1.w = acc[i][7];
        *(float4*)&C[(size_t)(m0 + i) * N + n0]     = o0;
        *(float4*)&C[(size_t)(m0 + i) * N + n0 + 4] = o1;
    }
}

// ---------------------------------------------------------------------------
// Fused bias: c[i] = sum_j qk_W[i,j]*q_b[j] + qk_W[i,512+j]*k_b[j] + qk_b[i]
// ---------------------------------------------------------------------------
__global__ void fuse_bias_kernel(float* __restrict__ c,
                                 const float* __restrict__ qk_W,
                                 const float* __restrict__ q_b,
                                 const float* __restrict__ k_b,
                                 const float* __restrict__ qk_b)
{
    int i = blockIdx.x * blockDim.x + threadIdx.x;
    if (i >= DA) return;
    float s = qk_b[i];
    const float* row = qk_W + (size_t)i * (2 * DA);
    for (int j = 0; j < DA; ++j)
        s += row[j] * q_b[j] + row[DA + j] * k_b[j];
    c[i] = s;
}

// ---------------------------------------------------------------------------
// Attention: one block per l. scores -> softmax -> y (emitted as fp16 hi/lo)
// ---------------------------------------------------------------------------
#define SS_LD 65

__global__ void __launch_bounds__(256) attention_kernel(
    const float* __restrict__ u,      // (B*L, 1024)
    const float* __restrict__ basis,  // (L, R, 1024)
    __half* __restrict__ yh, __half* __restrict__ yl)
{
    extern __shared__ float smf[];
    float* u_s = smf;                      // 16 * 1024
    float* s_s = smf + BB * DHID;          // 16 * SS_LD

    const int l    = blockIdx.x;
    const int t    = threadIdx.x;
    const int warp = t >> 5;
    const int lane = t & 31;
    const float scale = 0.044194173824159216f;  // 1/sqrt(512)

    for (int idx = t; idx < BB * DHID / 4; idx += 256) {
        int b  = idx >> 8;
        int d4 = idx & 255;
        *(float4*)&u_s[b * DHID + d4 * 4] =
            *(const float4*)&u[((size_t)b * LL + l) * DHID + d4 * 4];
    }
    __syncthreads();

    const float* basl = basis + (size_t)l * RR * DHID;

    for (int rr = 0; rr < 8; ++rr) {
        int r = warp * 8 + rr;
        const float* brow = basl + (size_t)r * DHID;
        float bas[32];
        #pragma unroll
        for (int i = 0; i < 32; ++i) bas[i] = brow[lane + 32 * i];
        #pragma unroll
        for (int b = 0; b < BB; ++b) {
            float p = 0.f;
            const float* ur = &u_s[b * DHID];
            #pragma unroll
            for (int i = 0; i < 32; ++i) p += bas[i] * ur[lane + 32 * i];
            #pragma unroll
            for (int o = 16; o; o >>= 1) p += __shfl_xor_sync(0xffffffffu, p, o);
            if (lane == 0) s_s[b * SS_LD + r] = p * scale;
        }
    }
    __syncthreads();

    {
        int b0 = warp * 2;
        #pragma unroll
        for (int bi = 0; bi < 2; ++bi) {
            int b = b0 + bi;
            float v0 = s_s[b * SS_LD + lane];
            float v1 = s_s[b * SS_LD + lane + 32];
            float mx = fmaxf(v0, v1);
            #pragma unroll
            for (int o = 16; o; o >>= 1) mx = fmaxf(mx, __shfl_xor_sync(0xffffffffu, mx, o));
            float e0 = __expf(v0 - mx);
            float e1 = __expf(v1 - mx);
            float sum = e0 + e1;
            #pragma unroll
            for (int o = 16; o; o >>= 1) sum += __shfl_xor_sync(0xffffffffu, sum, o);
            float inv = 1.f / sum;
            s_s[b * SS_LD + lane]      = e0 * inv;
            s_s[b * SS_LD + lane + 32] = e1 * inv;
        }
    }
    __syncthreads();

    for (int i = 0; i < 4; ++i) {
        int d = i * 256 + t;
        float acc[BB];
        #pragma unroll
        for (int b = 0; b < BB; ++b) acc[b] = 0.f;
        #pragma unroll 4
        for (int r = 0; r < RR; ++r) {
            float bv = basl[(size_t)r * DHID + d];
            #pragma unroll
            for (int b = 0; b < BB; ++b)
                acc[b] += s_s[b * SS_LD + r] * bv;
        }
        #pragma unroll
        for (int b = 0; b < BB; ++b) {
            size_t off = ((size_t)b * LL + l) * DHID + d;
            __half h = __float2half_rn(acc[b]);
            yh[off] = h;
            yl[off] = __float2half_rn(acc[b] - __half2float(h));
        }
    }
}

// ---------------------------------------------------------------------------
// Launch
// ---------------------------------------------------------------------------
extern "C" void kernel_launch(void* const* d_in, const int* in_sizes, int n_in,
                              void* d_out, int out_size)
{
    const float* s_emb  = (const float*)d_in[0];
    const float* t_emb  = (const float*)d_in[1];
    const float* basis  = (const float*)d_in[2];
    const float* q_W    = (const float*)d_in[3];
    const float* q_b    = (const float*)d_in[4];
    const float* k_W    = (const float*)d_in[5];
    const float* k_b    = (const float*)d_in[6];
    const float* qk_W   = (const float*)d_in[7];
    const float* qk_b   = (const float*)d_in[8];
    const float* bk_W   = (const float*)d_in[9];
    // d_in[10] = bk_b : provably unused (softmax shift invariance)
    const float* bv_W   = (const float*)d_in[11];
    const float* bv_b   = (const float*)d_in[12];
    float* out = (float*)d_out;

    float  *p_u, *p_A, *p_Bm, *p_c, *p_bkT;
    __half *p_sh, *p_th, *p_qh, *p_yh, *p_yl;
    __half *p_Ah, *p_Bmh, *p_bkTh, *p_bvh;
    cudaGetSymbolAddress((void**)&p_u,    g_u);
    cudaGetSymbolAddress((void**)&p_A,    g_A);
    cudaGetSymbolAddress((void**)&p_Bm,   g_Bm);
    cudaGetSymbolAddress((void**)&p_c,    g_c);
    cudaGetSymbolAddress((void**)&p_bkT,  g_bkT);
    cudaGetSymbolAddress((void**)&p_sh,   g_sh);
    cudaGetSymbolAddress((void**)&p_th,   g_th);
    cudaGetSymbolAddress((void**)&p_qh,   g_qh);
    cudaGetSymbolAddress((void**)&p_yh,   g_yh);
    cudaGetSymbolAddress((void**)&p_yl,   g_yl);
    cudaGetSymbolAddress((void**)&p_Ah,   g_Ah);
    cudaGetSymbolAddress((void**)&p_Bmh,  g_Bmh);
    cudaGetSymbolAddress((void**)&p_bkTh, g_bkTh);
    cudaGetSymbolAddress((void**)&p_bvh,  g_bvh);

    const int att_smem = (BB * DHID + BB * SS_LD) * (int)sizeof(float);
    cudaFuncSetAttribute(attention_kernel,
                         cudaFuncAttributeMaxDynamicSharedMemorySize, att_smem);
    cudaFuncSetAttribute(gemm_h_nt<true>,
                         cudaFuncAttributeMaxDynamicSharedMemorySize, SMEM_LO);
    cudaFuncSetAttribute(gemm_h_nt<false>,
                         cudaFuncAttributeMaxDynamicSharedMemorySize, SMEM_HI);

    // 1) Prep: fused projection matrices + bias + bk_W transpose (fp32)
    {
        dim3 grid(DHID / BN, DA / BM);
        gemm_nn_kernel<<<grid, 256>>>(p_A,  qk_W,      q_W, DA, DHID, DA, 2 * DA);
        gemm_nn_kernel<<<grid, 256>>>(p_Bm, qk_W + DA, k_W, DA, DHID, DA, 2 * DA);
        fuse_bias_kernel<<<1, DA>>>(p_c, qk_W, q_b, k_b, qk_b);
        dim3 tg(DHID / 32, DA / 32);
        transpose_kernel<<<tg, dim3(32, 8)>>>(p_bkT, bk_W, DA, DHID);
    }

    // 2) Converts: activations + weights -> fp16
    {
        const int ne = MTOT * DHID;                   // 33.5M
        cvt32to16<<<ne / 4 / 256, 256>>>(p_sh, s_emb, ne);
        cvt32to16<<<ne / 4 / 256, 256>>>(p_th, t_emb, ne);
        const int nw = DA * DHID;                     // 524288
        cvt32to16<<<nw / 4 / 256, 256>>>(p_Ah,   p_A,   nw);
        cvt32to16<<<nw / 4 / 256, 256>>>(p_Bmh,  p_Bm,  nw);
        cvt32to16<<<nw / 4 / 256, 256>>>(p_bkTh, p_bkT, nw);
        cvt32to16<<<nw / 4 / 256, 256>>>(p_bvh,  bv_W,  nw);
    }

    // 3) qk = s@A^T + t@Bm^T + c  (32768x512, K=1024x2, 1-pass)  -> fp16
    {
        GArgs ga = { p_sh, nullptr, p_Ah, p_th, nullptr, p_Bmh, DHID, DHID };
        dim3 grid(DA / 128, MTOT / 128);
        gemm_h_nt<false><<<grid, 256, SMEM_HI>>>(ga, p_c, nullptr, p_qh, nullptr,
                                                 MTOT, DA);
    }

    // 4) u = qk @ bkT^T  (32768x1024, K=512, 1-pass)  -> fp32
    {
        GArgs ga = { p_qh, nullptr, p_bkTh, nullptr, nullptr, nullptr, DA, 0 };
        dim3 grid(DHID / 128, MTOT / 128);
        gemm_h_nt<false><<<grid, 256, SMEM_HI>>>(ga, nullptr, p_u, nullptr, nullptr,
                                                 MTOT, DHID);
    }

    // 5) attention: scores -> softmax -> y (fp16 hi/lo)
    attention_kernel<<<LL, 256, att_smem>>>(p_u, basis, p_yh, p_yl);

    // 6) z = y @ bv_W^T + bv_b  (32768x512, K=1024, 2-pass)  -> fp32 out
    {
        GArgs ga = { p_yh, p_yl, p_bvh, nullptr, nullptr, nullptr, DHID, 0 };
        dim3 grid(DA / 128, MTOT / 128);
        gemm_h_nt<true><<<grid, 256, SMEM_LO>>>(ga, bv_b, out, nullptr, nullptr,
                                                MTOT, DA);
    }
}

// round 7
// speedup vs baseline: 2.7973x; 1.0591x over previous
#include <cuda_runtime.h>
#include <cuda_fp16.h>
#include <math.h>
#include <stdint.h>

// Problem constants
#define DHID 1024
#define DA   512
#define BB   16
#define LL   2048
#define RR   64
#define MTOT (BB*LL)   // 32768

// ---------------------------------------------------------------------------
// Scratch (static device globals; no allocations allowed)
// ---------------------------------------------------------------------------
__device__ __half g_sh [(size_t)MTOT * DHID];  // student fp16
__device__ __half g_th [(size_t)MTOT * DHID];  // teacher fp16
__device__ __half g_qh [(size_t)MTOT * DA];    // qk fp16
__device__ __half g_uh [(size_t)MTOT * DHID];  // u fp16
__device__ __half g_yh [(size_t)MTOT * DHID];  // y hi
__device__ __half g_yl [(size_t)MTOT * DHID];  // y lo
__device__ float  g_c  [DA];                   // fused bias (fp32)
__device__ __half g_Ah  [DA * DHID];           // fused qk_W1 @ q_W (fp16)
__device__ __half g_Bmh [DA * DHID];           // fused qk_W2 @ k_W (fp16)
__device__ __half g_bkTh[DHID * DA];           // bk_W transposed (fp16)
__device__ __half g_bvh [DA * DHID];           // bv_W (fp16)

// ---------------------------------------------------------------------------
// mma / ldmatrix helpers
// ---------------------------------------------------------------------------
__device__ __forceinline__ void mma_f16(float* c, const uint32_t* a,
                                        uint32_t b0, uint32_t b1)
{
    asm volatile(
        "mma.sync.aligned.m16n8k16.row.col.f32.f16.f16.f32 "
        "{%0,%1,%2,%3}, {%4,%5,%6,%7}, {%8,%9}, {%0,%1,%2,%3};\n"
        : "+f"(c[0]), "+f"(c[1]), "+f"(c[2]), "+f"(c[3])
        : "r"(a[0]), "r"(a[1]), "r"(a[2]), "r"(a[3]), "r"(b0), "r"(b1));
}

__device__ __forceinline__ void ldm_x4(uint32_t* r, uint32_t addr)
{
    asm volatile(
        "ldmatrix.sync.aligned.m8n8.x4.shared.b16 {%0,%1,%2,%3}, [%4];\n"
        : "=r"(r[0]), "=r"(r[1]), "=r"(r[2]), "=r"(r[3]) : "r"(addr));
}

__device__ __forceinline__ uint32_t smem_u32(const void* p) {
    uint32_t a;
    asm("{ .reg .u64 t; cvta.to.shared.u64 t, %1; cvt.u32.u64 %0, t; }"
        : "=r"(a) : "l"(p));
    return a;
}

#define CP_ASYNC16(dst, src) \
    asm volatile("cp.async.cg.shared.global [%0], [%1], 16;" \
                 :: "r"(dst), "l"(src) : "memory")
#define CP_COMMIT() asm volatile("cp.async.commit_group;" ::: "memory")
#define CP_WAIT1()  asm volatile("cp.async.wait_group 1;" ::: "memory")
#define CP_WAIT0()  asm volatile("cp.async.wait_group 0;" ::: "memory")

// ---------------------------------------------------------------------------
// fp16 GEMM (NT), K-chunk = 64; LO => activation hi/lo 2-pass.
//   C[m,n] = sum_k (Xh[+Xl])[m,k]*W[n,k] (over 1 or 2 input phases) + bias[n]
// Tile 128x128x64 per chunk; 8 warps of 32x64; cp.async pipeline
// (NSTAGE = LO ? 2 : 3); ldmatrix; smem rows 144 B (128 data + 16 pad).
// ---------------------------------------------------------------------------
#define ROWB   144
#define PLANE  (128 * ROWB)           // 18432 B
#define SMEM_G 110592                 // both variants: 110592 B -> occ 2

struct GArgs {
    const __half *Xh1, *Xl1, *W1;
    const __half *Xh2, *Xl2, *W2;
    int K1, K2;
};

template <bool LO>
__device__ __forceinline__ void load_stage(
    uint32_t sb, const __half* Xh, const __half* Xl, const __half* Wp,
    int ld, int bm, int bn, int k0, int t)
{
    const int NPL = LO ? 3 : 2;
    #pragma unroll
    for (int o = 0; o < 4 * NPL; ++o) {
        int idx   = t + o * 256;
        int plane = idx >> 10;            // 1024 ops per plane
        int p     = idx & 1023;
        int row   = p >> 3;
        int grp   = p & 7;                // 8 x 16B per 128B row
        uint32_t dst = sb + plane * PLANE + row * ROWB + grp * 16;
        const __half* src;
        if (LO) {
            if (plane == 0)      src = Xh + (size_t)(bm + row) * ld + k0 + grp * 8;
            else if (plane == 1) src = Xl + (size_t)(bm + row) * ld + k0 + grp * 8;
            else                 src = Wp + (size_t)(bn + row) * ld + k0 + grp * 8;
        } else {
            if (plane == 0)      src = Xh + (size_t)(bm + row) * ld + k0 + grp * 8;
            else                 src = Wp + (size_t)(bn + row) * ld + k0 + grp * 8;
        }
        CP_ASYNC16(dst, src);
    }
}

template <bool LO>
__global__ void __launch_bounds__(256, 2) gemm_h_nt(
    GArgs ga,
    const float* __restrict__ bias,
    float* __restrict__ Cf,               // fp32 out (nullable)
    __half* __restrict__ Ch,              // fp16 hi out (if Cf null)
    __half* __restrict__ Cl,              // fp16 lo out (nullable)
    int M, int N)
{
    extern __shared__ __align__(16) char smraw[];
    const uint32_t sm0    = smem_u32(smraw);
    const int      NSTAGE = LO ? 2 : 3;
    const uint32_t STAGEB = (LO ? 3 : 2) * PLANE;
    const uint32_t BPOFF  = (LO ? 2 : 1) * PLANE;

    const int t    = threadIdx.x;
    const int warp = t >> 5;
    const int lane = t & 31;
    const int bm   = blockIdx.y * 128;
    const int bn   = blockIdx.x * 128;
    const int mw   = (warp & 3) * 32;
    const int nw   = (warp >> 2) * 64;
    const uint32_t laneoff = (lane & 15) * ROWB + (lane >> 4) * 16;

    const int nc1 = ga.K1 / 64;
    const int nch = ga.Xh2 ? nc1 + ga.K2 / 64 : nc1;

    float acc[2][8][4];
    #pragma unroll
    for (int i = 0; i < 2; ++i)
        #pragma unroll
        for (int j = 0; j < 8; ++j)
            #pragma unroll
            for (int e = 0; e < 4; ++e) acc[i][j][e] = 0.f;

    // Prologue: stages 0, 1
    #pragma unroll
    for (int c = 0; c < 2; ++c) {
        if (c < nch) {
            if (c < nc1)
                load_stage<LO>(sm0 + c * STAGEB, ga.Xh1, ga.Xl1, ga.W1, ga.K1,
                               bm, bn, c * 64, t);
            else
                load_stage<LO>(sm0 + c * STAGEB, ga.Xh2, ga.Xl2, ga.W2, ga.K2,
                               bm, bn, (c - nc1) * 64, t);
            CP_COMMIT();
        }
    }

    for (int c = 0; c < nch; ++c) {
        if (c + 2 <= nch) CP_WAIT1(); else CP_WAIT0();
        __syncthreads();

        const uint32_t sb = sm0 + (c % NSTAGE) * STAGEB;
        #pragma unroll
        for (int ks = 0; ks < 4; ++ks) {
            const uint32_t kb = ks * 32;   // 16 halves = 32 bytes per k-step
            uint32_t ah0[4], ah1[4], al0[4], al1[4], bb[4][4];
            const uint32_t aA = sb + mw * ROWB + laneoff + kb;
            ldm_x4(ah0, aA);
            ldm_x4(ah1, aA + 16 * ROWB);
            if (LO) {
                ldm_x4(al0, aA + PLANE);
                ldm_x4(al1, aA + PLANE + 16 * ROWB);
            }
            const uint32_t bA = sb + BPOFF + nw * ROWB + laneoff + kb;
            #pragma unroll
            for (int j = 0; j < 4; ++j) ldm_x4(bb[j], bA + j * 16 * ROWB);

            #pragma unroll
            for (int i = 0; i < 2; ++i) {
                const uint32_t* ah = i ? ah1 : ah0;
                const uint32_t* al = i ? al1 : al0;
                #pragma unroll
                for (int j8 = 0; j8 < 8; ++j8) {
                    uint32_t b0 = bb[j8 >> 1][j8 & 1];
                    uint32_t b1 = bb[j8 >> 1][(j8 & 1) + 2];
                    mma_f16(acc[i][j8], ah, b0, b1);
                    if (LO) mma_f16(acc[i][j8], al, b0, b1);
                }
            }
        }
        __syncthreads();

        if (c + 2 < nch) {
            const int cn = c + 2;
            const uint32_t db = sm0 + (cn % NSTAGE) * STAGEB;
            if (cn < nc1)
                load_stage<LO>(db, ga.Xh1, ga.Xl1, ga.W1, ga.K1, bm, bn,
                               cn * 64, t);
            else
                load_stage<LO>(db, ga.Xh2, ga.Xl2, ga.W2, ga.K2, bm, bn,
                               (cn - nc1) * 64, t);
            CP_COMMIT();
        }
    }

    // Epilogue
    const int g = lane >> 2;
    const int q = lane & 3;
    #pragma unroll
    for (int i = 0; i < 2; ++i) {
        #pragma unroll
        for (int j8 = 0; j8 < 8; ++j8) {
            const int r0  = bm + mw + 16 * i + g;
            const int col = bn + nw + 8 * j8 + 2 * q;
            const float b0v = bias ? bias[col]     : 0.f;
            const float b1v = bias ? bias[col + 1] : 0.f;
            float v00 = acc[i][j8][0] + b0v, v01 = acc[i][j8][1] + b1v;
            float v10 = acc[i][j8][2] + b0v, v11 = acc[i][j8][3] + b1v;
            if (Cf) {
                *(float2*)&Cf[(size_t)r0 * N + col]       = make_float2(v00, v01);
                *(float2*)&Cf[(size_t)(r0 + 8) * N + col] = make_float2(v10, v11);
            } else {
                __half h00 = __float2half_rn(v00), h01 = __float2half_rn(v01);
                __half h10 = __float2half_rn(v10), h11 = __float2half_rn(v11);
                *(__half2*)&Ch[(size_t)r0 * N + col]       = __halves2half2(h00, h01);
                *(__half2*)&Ch[(size_t)(r0 + 8) * N + col] = __halves2half2(h10, h11);
                if (Cl) {
                    __half l00 = __float2half_rn(v00 - __half2float(h00));
                    __half l01 = __float2half_rn(v01 - __half2float(h01));
                    __half l10 = __float2half_rn(v10 - __half2float(h10));
                    __half l11 = __float2half_rn(v11 - __half2float(h11));
                    *(__half2*)&Cl[(size_t)r0 * N + col]       = __halves2half2(l00, l01);
                    *(__half2*)&Cl[(size_t)(r0 + 8) * N + col] = __halves2half2(l10, l11);
                }
            }
        }
    }
}

// ---------------------------------------------------------------------------
// Converter: fp32 -> fp16
// ---------------------------------------------------------------------------
__global__ void cvt32to16(__half* __restrict__ h, const float* __restrict__ s, int n)
{
    int i = (blockIdx.x * blockDim.x + threadIdx.x) * 4;
    if (i >= n) return;
    float4 v = *(const float4*)&s[i];
    *(__half2*)&h[i]     = __floats2half2_rn(v.x, v.y);
    *(__half2*)&h[i + 2] = __floats2half2_rn(v.z, v.w);
}

// ---------------------------------------------------------------------------
// Transpose (fp32 in -> fp16 out), once for bk_W
// ---------------------------------------------------------------------------
__global__ void transpose_h_kernel(__half* __restrict__ out,
                                   const float* __restrict__ in,
                                   int Rrows, int Ccols)
{
    __shared__ float tile[32][33];
    int x = blockIdx.x * 32 + threadIdx.x;
    int y = blockIdx.y * 32 + threadIdx.y;
    #pragma unroll
    for (int i = 0; i < 4; ++i)
        tile[threadIdx.y + 8 * i][threadIdx.x] = in[(size_t)(y + 8 * i) * Ccols + x];
    __syncthreads();
    x = blockIdx.y * 32 + threadIdx.x;
    y = blockIdx.x * 32 + threadIdx.y;
    #pragma unroll
    for (int i = 0; i < 4; ++i)
        out[(size_t)(y + 8 * i) * Rrows + x] =
            __float2half_rn(tile[threadIdx.x][threadIdx.y + 8 * i]);
}

// ---------------------------------------------------------------------------
// fp32 SIMT GEMM (NN), fp16 output — small prep GEMMs (512x1024x512).
// ---------------------------------------------------------------------------
#define BM 128
#define BN 128
#define BK 16

__global__ void __launch_bounds__(256, 2) gemm_nn_h_kernel(
    __half* __restrict__ C,
    const float* __restrict__ X, const float* __restrict__ W,
    int M, int N, int K, int ldx)
{
    __shared__ float As[BK][BM];
    __shared__ float Bs[BK][BN];
    const int t  = threadIdx.x;
    const int bm = blockIdx.y * BM;
    const int bn = blockIdx.x * BN;

    float acc[8][8];
    #pragma unroll
    for (int i = 0; i < 8; ++i)
        #pragma unroll
        for (int j = 0; j < 8; ++j) acc[i][j] = 0.f;

    const int lrow = t >> 2;
    const int lc4  = (t & 3) * 4;
    const int wk   = t >> 5;
    const int wn4  = (t & 31) * 4;

    for (int k0 = 0; k0 < K; k0 += BK) {
        #pragma unroll
        for (int h = 0; h < 2; ++h) {
            int row = lrow + h * 64;
            float4 v = *(const float4*)&X[(size_t)(bm + row) * ldx + k0 + lc4];
            As[lc4 + 0][row] = v.x;
            As[lc4 + 1][row] = v.y;
            As[lc4 + 2][row] = v.z;
            As[lc4 + 3][row] = v.w;
            int k = wk + h * 8;
            float4 w = *(const float4*)&W[(size_t)(k0 + k) * N + bn + wn4];
            *(float4*)&Bs[k][wn4] = w;
        }
        __syncthreads();
        const int m8 = (t >> 4) * 8;
        const int n8 = (t & 15) * 8;
        #pragma unroll
        for (int kk = 0; kk < BK; ++kk) {
            float a[8], b[8];
            *(float4*)&a[0] = *(const float4*)&As[kk][m8];
            *(float4*)&a[4] = *(const float4*)&As[kk][m8 + 4];
            *(float4*)&b[0] = *(const float4*)&Bs[kk][n8];
            *(float4*)&b[4] = *(const float4*)&Bs[kk][n8 + 4];
            #pragma unroll
            for (int i = 0; i < 8; ++i)
                #pragma unroll
                for (int j = 0; j < 8; ++j)
                    acc[i][j] += a[i] * b[j];
        }
        __syncthreads();
    }

    const int m0 = bm + (t >> 4) * 8;
    const int n0 = bn + (t & 15) * 8;
    #pragma unroll
    for (int i = 0; i < 8; ++i) {
        __half2 h0 = __floats2half2_rn(acc[i][0], acc[i][1]);
        __half2 h1 = __floats2half2_rn(acc[i][2], acc[i][3]);
        __half2 h2 = __floats2half2_rn(acc[i][4], acc[i][5]);
        __half2 h3 = __floats2half2_rn(acc[i][6], acc[i][7]);
        __half* dst = &C[(size_t)(m0 + i) * N + n0];
        *(__half2*)(dst + 0) = h0;
        *(__half2*)(dst + 2) = h1;
        *(__half2*)(dst + 4) = h2;
        *(__half2*)(dst + 6) = h3;
    }
}

// ---------------------------------------------------------------------------
// Fused bias: c[i] = sum_j qk_W[i,j]*q_b[j] + qk_W[i,512+j]*k_b[j] + qk_b[i]
// ---------------------------------------------------------------------------
__global__ void fuse_bias_kernel(float* __restrict__ c,
                                 const float* __restrict__ qk_W,
                                 const float* __restrict__ q_b,
                                 const float* __restrict__ k_b,
                                 const float* __restrict__ qk_b)
{
    int i = blockIdx.x * blockDim.x + threadIdx.x;
    if (i >= DA) return;
    float s = qk_b[i];
    const float* row = qk_W + (size_t)i * (2 * DA);
    for (int j = 0; j < DA; ++j)
        s += row[j] * q_b[j] + row[DA + j] * k_b[j];
    c[i] = s;
}

// ---------------------------------------------------------------------------
// Attention: one block per l. u is fp16; scores -> softmax -> y (fp16 hi/lo)
// ---------------------------------------------------------------------------
#define SS_LD 65

__global__ void __launch_bounds__(256) attention_kernel(
    const __half* __restrict__ u,     // (B*L, 1024) fp16
    const float* __restrict__ basis,  // (L, R, 1024)
    __half* __restrict__ yh, __half* __restrict__ yl)
{
    extern __shared__ float smf[];
    float* u_s = smf;                      // 16 * 1024 fp32
    float* s_s = smf + BB * DHID;          // 16 * SS_LD

    const int l    = blockIdx.x;
    const int t    = threadIdx.x;
    const int warp = t >> 5;
    const int lane = t & 31;
    const float scale = 0.044194173824159216f;  // 1/sqrt(512)

    // Load u tile (fp16, 8 halves per 16B op) -> fp32 smem
    for (int it = 0; it < 8; ++it) {
        int idx = t + it * 256;           // 0..2047
        int b   = idx >> 7;               // 128 groups of 8 per row
        int d8  = (idx & 127) * 8;
        uint4 raw = *(const uint4*)&u[((size_t)b * LL + l) * DHID + d8];
        const __half2* hp = (const __half2*)&raw;
        float* dst = &u_s[b * DHID + d8];
        #pragma unroll
        for (int k = 0; k < 4; ++k) {
            float2 f = __half22float2(hp[k]);
            dst[2 * k]     = f.x;
            dst[2 * k + 1] = f.y;
        }
    }
    __syncthreads();

    const float* basl = basis + (size_t)l * RR * DHID;

    for (int rr = 0; rr < 8; ++rr) {
        int r = warp * 8 + rr;
        const float* brow = basl + (size_t)r * DHID;
        float bas[32];
        #pragma unroll
        for (int i = 0; i < 32; ++i) bas[i] = brow[lane + 32 * i];
        #pragma unroll
        for (int b = 0; b < BB; ++b) {
            float p = 0.f;
            const float* ur = &u_s[b * DHID];
            #pragma unroll
            for (int i = 0; i < 32; ++i) p += bas[i] * ur[lane + 32 * i];
            #pragma unroll
            for (int o = 16; o; o >>= 1) p += __shfl_xor_sync(0xffffffffu, p, o);
            if (lane == 0) s_s[b * SS_LD + r] = p * scale;
        }
    }
    __syncthreads();

    {
        int b0 = warp * 2;
        #pragma unroll
        for (int bi = 0; bi < 2; ++bi) {
            int b = b0 + bi;
            float v0 = s_s[b * SS_LD + lane];
            float v1 = s_s[b * SS_LD + lane + 32];
            float mx = fmaxf(v0, v1);
            #pragma unroll
            for (int o = 16; o; o >>= 1) mx = fmaxf(mx, __shfl_xor_sync(0xffffffffu, mx, o));
            float e0 = __expf(v0 - mx);
            float e1 = __expf(v1 - mx);
            float sum = e0 + e1;
            #pragma unroll
            for (int o = 16; o; o >>= 1) sum += __shfl_xor_sync(0xffffffffu, sum, o);
            float inv = 1.f / sum;
            s_s[b * SS_LD + lane]      = e0 * inv;
            s_s[b * SS_LD + lane + 32] = e1 * inv;
        }
    }
    __syncthreads();

    for (int i = 0; i < 4; ++i) {
        int d = i * 256 + t;
        float acc[BB];
        #pragma unroll
        for (int b = 0; b < BB; ++b) acc[b] = 0.f;
        #pragma unroll 4
        for (int r = 0; r < RR; ++r) {
            float bv = basl[(size_t)r * DHID + d];
            #pragma unroll
            for (int b = 0; b < BB; ++b)
                acc[b] += s_s[b * SS_LD + r] * bv;
        }
        #pragma unroll
        for (int b = 0; b < BB; ++b) {
            size_t off = ((size_t)b * LL + l) * DHID + d;
            __half h = __float2half_rn(acc[b]);
            yh[off] = h;
            yl[off] = __float2half_rn(acc[b] - __half2float(h));
        }
    }
}

// ---------------------------------------------------------------------------
// Launch
// ---------------------------------------------------------------------------
extern "C" void kernel_launch(void* const* d_in, const int* in_sizes, int n_in,
                              void* d_out, int out_size)
{
    const float* s_emb  = (const float*)d_in[0];
    const float* t_emb  = (const float*)d_in[1];
    const float* basis  = (const float*)d_in[2];
    const float* q_W    = (const float*)d_in[3];
    const float* q_b    = (const float*)d_in[4];
    const float* k_W    = (const float*)d_in[5];
    const float* k_b    = (const float*)d_in[6];
    const float* qk_W   = (const float*)d_in[7];
    const float* qk_b   = (const float*)d_in[8];
    const float* bk_W   = (const float*)d_in[9];
    // d_in[10] = bk_b : provably unused (softmax shift invariance)
    const float* bv_W   = (const float*)d_in[11];
    const float* bv_b   = (const float*)d_in[12];
    float* out = (float*)d_out;

    float  *p_c;
    __half *p_sh, *p_th, *p_qh, *p_uh, *p_yh, *p_yl;
    __half *p_Ah, *p_Bmh, *p_bkTh, *p_bvh;
    cudaGetSymbolAddress((void**)&p_c,    g_c);
    cudaGetSymbolAddress((void**)&p_sh,   g_sh);
    cudaGetSymbolAddress((void**)&p_th,   g_th);
    cudaGetSymbolAddress((void**)&p_qh,   g_qh);
    cudaGetSymbolAddress((void**)&p_uh,   g_uh);
    cudaGetSymbolAddress((void**)&p_yh,   g_yh);
    cudaGetSymbolAddress((void**)&p_yl,   g_yl);
    cudaGetSymbolAddress((void**)&p_Ah,   g_Ah);
    cudaGetSymbolAddress((void**)&p_Bmh,  g_Bmh);
    cudaGetSymbolAddress((void**)&p_bkTh, g_bkTh);
    cudaGetSymbolAddress((void**)&p_bvh,  g_bvh);

    const int att_smem = (BB * DHID + BB * SS_LD) * (int)sizeof(float);
    cudaFuncSetAttribute(attention_kernel,
                         cudaFuncAttributeMaxDynamicSharedMemorySize, att_smem);
    cudaFuncSetAttribute(gemm_h_nt<true>,
                         cudaFuncAttributeMaxDynamicSharedMemorySize, SMEM_G);
    cudaFuncSetAttribute(gemm_h_nt<false>,
                         cudaFuncAttributeMaxDynamicSharedMemorySize, SMEM_G);

    // 1) Prep: fused projection matrices (fp16 out) + bias + bk_W transpose
    {
        dim3 grid(DHID / BN, DA / BM);
        gemm_nn_h_kernel<<<grid, 256>>>(p_Ah,  qk_W,      q_W, DA, DHID, DA, 2 * DA);
        gemm_nn_h_kernel<<<grid, 256>>>(p_Bmh, qk_W + DA, k_W, DA, DHID, DA, 2 * DA);
        fuse_bias_kernel<<<1, DA>>>(p_c, qk_W, q_b, k_b, qk_b);
        dim3 tg(DHID / 32, DA / 32);
        transpose_h_kernel<<<tg, dim3(32, 8)>>>(p_bkTh, bk_W, DA, DHID);
    }

    // 2) Converts: activations + bv_W -> fp16
    {
        const int ne = MTOT * DHID;                   // 33.5M
        cvt32to16<<<ne / 4 / 256, 256>>>(p_sh, s_emb, ne);
        cvt32to16<<<ne / 4 / 256, 256>>>(p_th, t_emb, ne);
        const int nw = DA * DHID;
        cvt32to16<<<nw / 4 / 256, 256>>>(p_bvh, bv_W, nw);
    }

    // 3) qk = s@A^T + t@Bm^T + c  (32768x512, K=1024x2, 1-pass)  -> fp16
    {
        GArgs ga = { p_sh, nullptr, p_Ah, p_th, nullptr, p_Bmh, DHID, DHID };
        dim3 grid(DA / 128, MTOT / 128);
        gemm_h_nt<false><<<grid, 256, SMEM_G>>>(ga, p_c, nullptr, p_qh, nullptr,
                                                MTOT, DA);
    }

    // 4) u = qk @ bkT^T  (32768x1024, K=512, 1-pass)  -> fp16
    {
        GArgs ga = { p_qh, nullptr, p_bkTh, nullptr, nullptr, nullptr, DA, 0 };
        dim3 grid(DHID / 128, MTOT / 128);
        gemm_h_nt<false><<<grid, 256, SMEM_G>>>(ga, nullptr, nullptr, p_uh, nullptr,
                                                MTOT, DHID);
    }

    // 5) attention: scores -> softmax -> y (fp16 hi/lo)
    attention_kernel<<<LL, 256, att_smem>>>(p_uh, basis, p_yh, p_yl);

    // 6) z = y @ bv_W^T + bv_b  (32768x512, K=1024, 2-pass)  -> fp32 out
    {
        GArgs ga = { p_yh, p_yl, p_bvh, nullptr, nullptr, nullptr, DHID, 0 };
        dim3 grid(DA / 128, MTOT / 128);
        gemm_h_nt<true><<<grid, 256, SMEM_G>>>(ga, bv_b, out, nullptr, nullptr,
                                               MTOT, DA);
    }
}

// round 8
// speedup vs baseline: 2.9801x; 1.0654x over previous
#include <cuda_runtime.h>
#include <cuda_fp16.h>
#include <math.h>
#include <stdint.h>

// Problem constants
#define DHID 1024
#define DA   512
#define BB   16
#define LL   2048
#define RR   64
#define MTOT (BB*LL)   // 32768

// ---------------------------------------------------------------------------
// Scratch (static device globals; no allocations allowed)
// ---------------------------------------------------------------------------
__device__ __half g_sh [(size_t)MTOT * DHID];  // student fp16
__device__ __half g_th [(size_t)MTOT * DHID];  // teacher fp16
__device__ __half g_qh [(size_t)MTOT * DA];    // qk fp16
__device__ __half g_uh [(size_t)MTOT * DHID];  // u fp16
__device__ __half g_yh [(size_t)MTOT * DHID];  // y fp16
__device__ float  g_c  [DA];                   // fused bias (fp32)
__device__ __half g_Ah  [DA * DHID];           // fused qk_W1 @ q_W (fp16)
__device__ __half g_Bmh [DA * DHID];           // fused qk_W2 @ k_W (fp16)
__device__ __half g_bkTh[DHID * DA];           // bk_W transposed (fp16)
__device__ __half g_bvh [DA * DHID];           // bv_W (fp16)

// ---------------------------------------------------------------------------
// mma / ldmatrix helpers
// ---------------------------------------------------------------------------
__device__ __forceinline__ void mma_f16(float* c, const uint32_t* a,
                                        uint32_t b0, uint32_t b1)
{
    asm volatile(
        "mma.sync.aligned.m16n8k16.row.col.f32.f16.f16.f32 "
        "{%0,%1,%2,%3}, {%4,%5,%6,%7}, {%8,%9}, {%0,%1,%2,%3};\n"
        : "+f"(c[0]), "+f"(c[1]), "+f"(c[2]), "+f"(c[3])
        : "r"(a[0]), "r"(a[1]), "r"(a[2]), "r"(a[3]), "r"(b0), "r"(b1));
}

__device__ __forceinline__ void ldm_x4(uint32_t* r, uint32_t addr)
{
    asm volatile(
        "ldmatrix.sync.aligned.m8n8.x4.shared.b16 {%0,%1,%2,%3}, [%4];\n"
        : "=r"(r[0]), "=r"(r[1]), "=r"(r[2]), "=r"(r[3]) : "r"(addr));
}

__device__ __forceinline__ uint32_t smem_u32(const void* p) {
    uint32_t a;
    asm("{ .reg .u64 t; cvta.to.shared.u64 t, %1; cvt.u32.u64 %0, t; }"
        : "=r"(a) : "l"(p));
    return a;
}

#define CP_ASYNC16(dst, src) \
    asm volatile("cp.async.cg.shared.global [%0], [%1], 16;" \
                 :: "r"(dst), "l"(src) : "memory")
#define CP_COMMIT() asm volatile("cp.async.commit_group;" ::: "memory")
#define CP_WAIT1()  asm volatile("cp.async.wait_group 1;" ::: "memory")
#define CP_WAIT0()  asm volatile("cp.async.wait_group 0;" ::: "memory")

// ---------------------------------------------------------------------------
// fp16 GEMM (NT), K-chunk = 64, single pass:
//   C[m,n] = sum_k Xh1[m,k]*W1[n,k] (+ Xh2*W2 phase) + bias[n]
// Tile 128x128x64 per chunk; 8 warps of 32x64; 3-stage cp.async pipeline;
// ldmatrix; smem rows 144 B (128 data + 16 pad).
// ---------------------------------------------------------------------------
#define ROWB   144
#define PLANE  (128 * ROWB)           // 18432 B
#define NSTAGE 3
#define SMEM_G (NSTAGE * 2 * PLANE)   // 110592 B -> occ 2

struct GArgs {
    const __half *X1, *W1;
    const __half *X2, *W2;
    int K1, K2;
};

__device__ __forceinline__ void load_stage(
    uint32_t sb, const __half* Xh, const __half* Wp,
    int ld, int bm, int bn, int k0, int t)
{
    #pragma unroll
    for (int o = 0; o < 8; ++o) {
        int idx   = t + o * 256;
        int plane = idx >> 10;            // 1024 ops per plane
        int p     = idx & 1023;
        int row   = p >> 3;
        int grp   = p & 7;                // 8 x 16B per 128B row
        uint32_t dst = sb + plane * PLANE + row * ROWB + grp * 16;
        const __half* src = (plane == 0)
            ? Xh + (size_t)(bm + row) * ld + k0 + grp * 8
            : Wp + (size_t)(bn + row) * ld + k0 + grp * 8;
        CP_ASYNC16(dst, src);
    }
}

__global__ void __launch_bounds__(256, 2) gemm_h_nt(
    GArgs ga,
    const float* __restrict__ bias,
    float* __restrict__ Cf,               // fp32 out (nullable)
    __half* __restrict__ Ch,              // fp16 out (if Cf null)
    int M, int N)
{
    extern __shared__ __align__(16) char smraw[];
    const uint32_t sm0 = smem_u32(smraw);

    const int t    = threadIdx.x;
    const int warp = t >> 5;
    const int lane = t & 31;
    const int bm   = blockIdx.y * 128;
    const int bn   = blockIdx.x * 128;
    const int mw   = (warp & 3) * 32;
    const int nw   = (warp >> 2) * 64;
    const uint32_t laneoff = (lane & 15) * ROWB + (lane >> 4) * 16;

    const int nc1 = ga.K1 / 64;
    const int nch = ga.X2 ? nc1 + ga.K2 / 64 : nc1;

    float acc[2][8][4];
    #pragma unroll
    for (int i = 0; i < 2; ++i)
        #pragma unroll
        for (int j = 0; j < 8; ++j)
            #pragma unroll
            for (int e = 0; e < 4; ++e) acc[i][j][e] = 0.f;

    // Prologue: stages 0, 1
    #pragma unroll
    for (int c = 0; c < 2; ++c) {
        if (c < nch) {
            if (c < nc1)
                load_stage(sm0 + c * 2 * PLANE, ga.X1, ga.W1, ga.K1,
                           bm, bn, c * 64, t);
            else
                load_stage(sm0 + c * 2 * PLANE, ga.X2, ga.W2, ga.K2,
                           bm, bn, (c - nc1) * 64, t);
            CP_COMMIT();
        }
    }

    for (int c = 0; c < nch; ++c) {
        if (c + 2 <= nch) CP_WAIT1(); else CP_WAIT0();
        __syncthreads();

        const uint32_t sb = sm0 + (c % NSTAGE) * 2 * PLANE;
        #pragma unroll
        for (int ks = 0; ks < 4; ++ks) {
            const uint32_t kb = ks * 32;   // 16 halves = 32 bytes per k-step
            uint32_t ah0[4], ah1[4], bb[4][4];
            const uint32_t aA = sb + mw * ROWB + laneoff + kb;
            ldm_x4(ah0, aA);
            ldm_x4(ah1, aA + 16 * ROWB);
            const uint32_t bA = sb + PLANE + nw * ROWB + laneoff + kb;
            #pragma unroll
            for (int j = 0; j < 4; ++j) ldm_x4(bb[j], bA + j * 16 * ROWB);

            #pragma unroll
            for (int i = 0; i < 2; ++i) {
                const uint32_t* ah = i ? ah1 : ah0;
                #pragma unroll
                for (int j8 = 0; j8 < 8; ++j8) {
                    uint32_t b0 = bb[j8 >> 1][j8 & 1];
                    uint32_t b1 = bb[j8 >> 1][(j8 & 1) + 2];
                    mma_f16(acc[i][j8], ah, b0, b1);
                }
            }
        }
        __syncthreads();

        if (c + 2 < nch) {
            const int cn = c + 2;
            const uint32_t db = sm0 + (cn % NSTAGE) * 2 * PLANE;
            if (cn < nc1)
                load_stage(db, ga.X1, ga.W1, ga.K1, bm, bn, cn * 64, t);
            else
                load_stage(db, ga.X2, ga.W2, ga.K2, bm, bn,
                           (cn - nc1) * 64, t);
            CP_COMMIT();
        }
    }

    // Epilogue
    const int g = lane >> 2;
    const int q = lane & 3;
    #pragma unroll
    for (int i = 0; i < 2; ++i) {
        #pragma unroll
        for (int j8 = 0; j8 < 8; ++j8) {
            const int r0  = bm + mw + 16 * i + g;
            const int col = bn + nw + 8 * j8 + 2 * q;
            const float b0v = bias ? bias[col]     : 0.f;
            const float b1v = bias ? bias[col + 1] : 0.f;
            float v00 = acc[i][j8][0] + b0v, v01 = acc[i][j8][1] + b1v;
            float v10 = acc[i][j8][2] + b0v, v11 = acc[i][j8][3] + b1v;
            if (Cf) {
                *(float2*)&Cf[(size_t)r0 * N + col]       = make_float2(v00, v01);
                *(float2*)&Cf[(size_t)(r0 + 8) * N + col] = make_float2(v10, v11);
            } else {
                *(__half2*)&Ch[(size_t)r0 * N + col]       = __floats2half2_rn(v00, v01);
                *(__half2*)&Ch[(size_t)(r0 + 8) * N + col] = __floats2half2_rn(v10, v11);
            }
        }
    }
}

// ---------------------------------------------------------------------------
// Fused converter: s,t fp32 -> fp16 in one launch
// ---------------------------------------------------------------------------
__global__ void cvt_pair32to16(__half* __restrict__ h0, const float* __restrict__ s0,
                               __half* __restrict__ h1, const float* __restrict__ s1,
                               int n)
{
    int i = (blockIdx.x * blockDim.x + threadIdx.x) * 4;
    if (i >= n) return;
    float4 a = *(const float4*)&s0[i];
    *(__half2*)&h0[i]     = __floats2half2_rn(a.x, a.y);
    *(__half2*)&h0[i + 2] = __floats2half2_rn(a.z, a.w);
    float4 b = *(const float4*)&s1[i];
    *(__half2*)&h1[i]     = __floats2half2_rn(b.x, b.y);
    *(__half2*)&h1[i + 2] = __floats2half2_rn(b.z, b.w);
}

__global__ void cvt32to16(__half* __restrict__ h, const float* __restrict__ s, int n)
{
    int i = (blockIdx.x * blockDim.x + threadIdx.x) * 4;
    if (i >= n) return;
    float4 v = *(const float4*)&s[i];
    *(__half2*)&h[i]     = __floats2half2_rn(v.x, v.y);
    *(__half2*)&h[i + 2] = __floats2half2_rn(v.z, v.w);
}

// ---------------------------------------------------------------------------
// Transpose (fp32 in -> fp16 out), once for bk_W
// ---------------------------------------------------------------------------
__global__ void transpose_h_kernel(__half* __restrict__ out,
                                   const float* __restrict__ in,
                                   int Rrows, int Ccols)
{
    __shared__ float tile[32][33];
    int x = blockIdx.x * 32 + threadIdx.x;
    int y = blockIdx.y * 32 + threadIdx.y;
    #pragma unroll
    for (int i = 0; i < 4; ++i)
        tile[threadIdx.y + 8 * i][threadIdx.x] = in[(size_t)(y + 8 * i) * Ccols + x];
    __syncthreads();
    x = blockIdx.y * 32 + threadIdx.x;
    y = blockIdx.x * 32 + threadIdx.y;
    #pragma unroll
    for (int i = 0; i < 4; ++i)
        out[(size_t)(y + 8 * i) * Rrows + x] =
            __float2half_rn(tile[threadIdx.x][threadIdx.y + 8 * i]);
}

// ---------------------------------------------------------------------------
// fp32 SIMT GEMM (NN), fp16 output — small prep GEMMs (512x1024x512).
// ---------------------------------------------------------------------------
#define BM 128
#define BN 128
#define BK 16

__global__ void __launch_bounds__(256, 2) gemm_nn_h_kernel(
    __half* __restrict__ C,
    const float* __restrict__ X, const float* __restrict__ W,
    int M, int N, int K, int ldx)
{
    __shared__ float As[BK][BM];
    __shared__ float Bs[BK][BN];
    const int t  = threadIdx.x;
    const int bm = blockIdx.y * BM;
    const int bn = blockIdx.x * BN;

    float acc[8][8];
    #pragma unroll
    for (int i = 0; i < 8; ++i)
        #pragma unroll
        for (int j = 0; j < 8; ++j) acc[i][j] = 0.f;

    const int lrow = t >> 2;
    const int lc4  = (t & 3) * 4;
    const int wk   = t >> 5;
    const int wn4  = (t & 31) * 4;

    for (int k0 = 0; k0 < K; k0 += BK) {
        #pragma unroll
        for (int h = 0; h < 2; ++h) {
            int row = lrow + h * 64;
            float4 v = *(const float4*)&X[(size_t)(bm + row) * ldx + k0 + lc4];
            As[lc4 + 0][row] = v.x;
            As[lc4 + 1][row] = v.y;
            As[lc4 + 2][row] = v.z;
            As[lc4 + 3][row] = v.w;
            int k = wk + h * 8;
            float4 w = *(const float4*)&W[(size_t)(k0 + k) * N + bn + wn4];
            *(float4*)&Bs[k][wn4] = w;
        }
        __syncthreads();
        const int m8 = (t >> 4) * 8;
        const int n8 = (t & 15) * 8;
        #pragma unroll
        for (int kk = 0; kk < BK; ++kk) {
            float a[8], b[8];
            *(float4*)&a[0] = *(const float4*)&As[kk][m8];
            *(float4*)&a[4] = *(const float4*)&As[kk][m8 + 4];
            *(float4*)&b[0] = *(const float4*)&Bs[kk][n8];
            *(float4*)&b[4] = *(const float4*)&Bs[kk][n8 + 4];
            #pragma unroll
            for (int i = 0; i < 8; ++i)
                #pragma unroll
                for (int j = 0; j < 8; ++j)
                    acc[i][j] += a[i] * b[j];
        }
        __syncthreads();
    }

    const int m0 = bm + (t >> 4) * 8;
    const int n0 = bn + (t & 15) * 8;
    #pragma unroll
    for (int i = 0; i < 8; ++i) {
        __half2 h0 = __floats2half2_rn(acc[i][0], acc[i][1]);
        __half2 h1 = __floats2half2_rn(acc[i][2], acc[i][3]);
        __half2 h2 = __floats2half2_rn(acc[i][4], acc[i][5]);
        __half2 h3 = __floats2half2_rn(acc[i][6], acc[i][7]);
        __half* dst = &C[(size_t)(m0 + i) * N + n0];
        *(__half2*)(dst + 0) = h0;
        *(__half2*)(dst + 2) = h1;
        *(__half2*)(dst + 4) = h2;
        *(__half2*)(dst + 6) = h3;
    }
}

// ---------------------------------------------------------------------------
// Fused bias: c[i] = sum_j qk_W[i,j]*q_b[j] + qk_W[i,512+j]*k_b[j] + qk_b[i]
// ---------------------------------------------------------------------------
__global__ void fuse_bias_kernel(float* __restrict__ c,
                                 const float* __restrict__ qk_W,
                                 const float* __restrict__ q_b,
                                 const float* __restrict__ k_b,
                                 const float* __restrict__ qk_b)
{
    int i = blockIdx.x * blockDim.x + threadIdx.x;
    if (i >= DA) return;
    float s = qk_b[i];
    const float* row = qk_W + (size_t)i * (2 * DA);
    for (int j = 0; j < DA; ++j)
        s += row[j] * q_b[j] + row[DA + j] * k_b[j];
    c[i] = s;
}

// ---------------------------------------------------------------------------
// Attention: one block per l. u fp16 in; scores -> softmax -> y (fp16)
// ---------------------------------------------------------------------------
#define SS_LD 65

__global__ void __launch_bounds__(256) attention_kernel(
    const __half* __restrict__ u,     // (B*L, 1024) fp16
    const float* __restrict__ basis,  // (L, R, 1024)
    __half* __restrict__ yh)
{
    extern __shared__ float smf[];
    float* u_s = smf;                      // 16 * 1024 fp32
    float* s_s = smf + BB * DHID;          // 16 * SS_LD

    const int l    = blockIdx.x;
    const int t    = threadIdx.x;
    const int warp = t >> 5;
    const int lane = t & 31;
    const float scale = 0.044194173824159216f;  // 1/sqrt(512)

    // Load u tile (fp16) -> fp32 smem
    for (int it = 0; it < 8; ++it) {
        int idx = t + it * 256;           // 0..2047
        int b   = idx >> 7;
        int d8  = (idx & 127) * 8;
        uint4 raw = *(const uint4*)&u[((size_t)b * LL + l) * DHID + d8];
        const __half2* hp = (const __half2*)&raw;
        float* dst = &u_s[b * DHID + d8];
        #pragma unroll
        for (int k = 0; k < 4; ++k) {
            float2 f = __half22float2(hp[k]);
            dst[2 * k]     = f.x;
            dst[2 * k + 1] = f.y;
        }
    }
    __syncthreads();

    const float* basl = basis + (size_t)l * RR * DHID;

    for (int rr = 0; rr < 8; ++rr) {
        int r = warp * 8 + rr;
        const float* brow = basl + (size_t)r * DHID;
        float bas[32];
        #pragma unroll
        for (int i = 0; i < 32; ++i) bas[i] = brow[lane + 32 * i];
        #pragma unroll
        for (int b = 0; b < BB; ++b) {
            float p = 0.f;
            const float* ur = &u_s[b * DHID];
            #pragma unroll
            for (int i = 0; i < 32; ++i) p += bas[i] * ur[lane + 32 * i];
            #pragma unroll
            for (int o = 16; o; o >>= 1) p += __shfl_xor_sync(0xffffffffu, p, o);
            if (lane == 0) s_s[b * SS_LD + r] = p * scale;
        }
    }
    __syncthreads();

    {
        int b0 = warp * 2;
        #pragma unroll
        for (int bi = 0; bi < 2; ++bi) {
            int b = b0 + bi;
            float v0 = s_s[b * SS_LD + lane];
            float v1 = s_s[b * SS_LD + lane + 32];
            float mx = fmaxf(v0, v1);
            #pragma unroll
            for (int o = 16; o; o >>= 1) mx = fmaxf(mx, __shfl_xor_sync(0xffffffffu, mx, o));
            float e0 = __expf(v0 - mx);
            float e1 = __expf(v1 - mx);
            float sum = e0 + e1;
            #pragma unroll
            for (int o = 16; o; o >>= 1) sum += __shfl_xor_sync(0xffffffffu, sum, o);
            float inv = 1.f / sum;
            s_s[b * SS_LD + lane]      = e0 * inv;
            s_s[b * SS_LD + lane + 32] = e1 * inv;
        }
    }
    __syncthreads();

    for (int i = 0; i < 4; ++i) {
        int d = i * 256 + t;
        float acc[BB];
        #pragma unroll
        for (int b = 0; b < BB; ++b) acc[b] = 0.f;
        #pragma unroll 4
        for (int r = 0; r < RR; ++r) {
            float bv = basl[(size_t)r * DHID + d];
            #pragma unroll
            for (int b = 0; b < BB; ++b)
                acc[b] += s_s[b * SS_LD + r] * bv;
        }
        #pragma unroll
        for (int b = 0; b < BB; ++b)
            yh[((size_t)b * LL + l) * DHID + d] = __float2half_rn(acc[b]);
    }
}

// ---------------------------------------------------------------------------
// Launch
// ---------------------------------------------------------------------------
extern "C" void kernel_launch(void* const* d_in, const int* in_sizes, int n_in,
                              void* d_out, int out_size)
{
    const float* s_emb  = (const float*)d_in[0];
    const float* t_emb  = (const float*)d_in[1];
    const float* basis  = (const float*)d_in[2];
    const float* q_W    = (const float*)d_in[3];
    const float* q_b    = (const float*)d_in[4];
    const float* k_W    = (const float*)d_in[5];
    const float* k_b    = (const float*)d_in[6];
    const float* qk_W   = (const float*)d_in[7];
    const float* qk_b   = (const float*)d_in[8];
    const float* bk_W   = (const float*)d_in[9];
    // d_in[10] = bk_b : provably unused (softmax shift invariance)
    const float* bv_W   = (const float*)d_in[11];
    const float* bv_b   = (const float*)d_in[12];
    float* out = (float*)d_out;

    float  *p_c;
    __half *p_sh, *p_th, *p_qh, *p_uh, *p_yh;
    __half *p_Ah, *p_Bmh, *p_bkTh, *p_bvh;
    cudaGetSymbolAddress((void**)&p_c,    g_c);
    cudaGetSymbolAddress((void**)&p_sh,   g_sh);
    cudaGetSymbolAddress((void**)&p_th,   g_th);
    cudaGetSymbolAddress((void**)&p_qh,   g_qh);
    cudaGetSymbolAddress((void**)&p_uh,   g_uh);
    cudaGetSymbolAddress((void**)&p_yh,   g_yh);
    cudaGetSymbolAddress((void**)&p_Ah,   g_Ah);
    cudaGetSymbolAddress((void**)&p_Bmh,  g_Bmh);
    cudaGetSymbolAddress((void**)&p_bkTh, g_bkTh);
    cudaGetSymbolAddress((void**)&p_bvh,  g_bvh);

    const int att_smem = (BB * DHID + BB * SS_LD) * (int)sizeof(float);
    cudaFuncSetAttribute(attention_kernel,
                         cudaFuncAttributeMaxDynamicSharedMemorySize, att_smem);
    cudaFuncSetAttribute(gemm_h_nt,
                         cudaFuncAttributeMaxDynamicSharedMemorySize, SMEM_G);

    // 1) Prep: fused projection matrices (fp16 out) + bias + bk_W transpose
    {
        dim3 grid(DHID / BN, DA / BM);
        gemm_nn_h_kernel<<<grid, 256>>>(p_Ah,  qk_W,      q_W, DA, DHID, DA, 2 * DA);
        gemm_nn_h_kernel<<<grid, 256>>>(p_Bmh, qk_W + DA, k_W, DA, DHID, DA, 2 * DA);
        fuse_bias_kernel<<<1, DA>>>(p_c, qk_W, q_b, k_b, qk_b);
        dim3 tg(DHID / 32, DA / 32);
        transpose_h_kernel<<<tg, dim3(32, 8)>>>(p_bkTh, bk_W, DA, DHID);
    }

    // 2) Converts: s+t fused; bv_W
    {
        const int ne = MTOT * DHID;                   // 33.5M
        cvt_pair32to16<<<ne / 4 / 256, 256>>>(p_sh, s_emb, p_th, t_emb, ne);
        const int nw = DA * DHID;
        cvt32to16<<<nw / 4 / 256, 256>>>(p_bvh, bv_W, nw);
    }

    // 3) qk = s@A^T + t@Bm^T + c  (32768x512, K=1024x2)  -> fp16
    {
        GArgs ga = { p_sh, p_Ah, p_th, p_Bmh, DHID, DHID };
        dim3 grid(DA / 128, MTOT / 128);
        gemm_h_nt<<<grid, 256, SMEM_G>>>(ga, p_c, nullptr, p_qh, MTOT, DA);
    }

    // 4) u = qk @ bkT^T  (32768x1024, K=512)  -> fp16
    {
        GArgs ga = { p_qh, p_bkTh, nullptr, nullptr, DA, 0 };
        dim3 grid(DHID / 128, MTOT / 128);
        gemm_h_nt<<<grid, 256, SMEM_G>>>(ga, nullptr, nullptr, p_uh, MTOT, DHID);
    }

    // 5) attention: scores -> softmax -> y (fp16)
    attention_kernel<<<LL, 256, att_smem>>>(p_uh, basis, p_yh);

    // 6) z = y @ bv_W^T + bv_b  (32768x512, K=1024)  -> fp32 out
    {
        GArgs ga = { p_yh, p_bvh, nullptr, nullptr, DHID, 0 };
        dim3 grid(DA / 128, MTOT / 128);
        gemm_h_nt<<<grid, 256, SMEM_G>>>(ga, bv_b, out, nullptr, MTOT, DA);
    }
}

// round 9
// speedup vs baseline: 3.1928x; 1.0714x over previous
#include <cuda_runtime.h>
#include <cuda_fp16.h>
#include <math.h>
#include <stdint.h>

// Problem constants
#define DHID 1024
#define DA   512
#define BB   16
#define LL   2048
#define RR   64
#define MTOT (BB*LL)   // 32768

// ---------------------------------------------------------------------------
// Scratch (static device globals; no allocations allowed)
// ---------------------------------------------------------------------------
__device__ __half g_sh [(size_t)MTOT * DHID];  // student fp16
__device__ __half g_th [(size_t)MTOT * DHID];  // teacher fp16
__device__ __half g_qh [(size_t)MTOT * DA];    // qk fp16
__device__ __half g_uh [(size_t)MTOT * DHID];  // u fp16
__device__ __half g_yh [(size_t)MTOT * DHID];  // y fp16
__device__ float  g_c  [DA];                   // fused bias (fp32)
__device__ __half g_Ah  [DA * DHID];           // fused qk_W1 @ q_W (fp16)
__device__ __half g_Bmh [DA * DHID];           // fused qk_W2 @ k_W (fp16)
__device__ __half g_bkTh[DHID * DA];           // bk_W transposed (fp16)
__device__ __half g_bvh [DA * DHID];           // bv_W (fp16)

// ---------------------------------------------------------------------------
// mma / ldmatrix helpers
// ---------------------------------------------------------------------------
__device__ __forceinline__ void mma_f16(float* c, const uint32_t* a,
                                        uint32_t b0, uint32_t b1)
{
    asm volatile(
        "mma.sync.aligned.m16n8k16.row.col.f32.f16.f16.f32 "
        "{%0,%1,%2,%3}, {%4,%5,%6,%7}, {%8,%9}, {%0,%1,%2,%3};\n"
        : "+f"(c[0]), "+f"(c[1]), "+f"(c[2]), "+f"(c[3])
        : "r"(a[0]), "r"(a[1]), "r"(a[2]), "r"(a[3]), "r"(b0), "r"(b1));
}

__device__ __forceinline__ void ldm_x4(uint32_t* r, uint32_t addr)
{
    asm volatile(
        "ldmatrix.sync.aligned.m8n8.x4.shared.b16 {%0,%1,%2,%3}, [%4];\n"
        : "=r"(r[0]), "=r"(r[1]), "=r"(r[2]), "=r"(r[3]) : "r"(addr));
}

__device__ __forceinline__ uint32_t smem_u32(const void* p) {
    uint32_t a;
    asm("{ .reg .u64 t; cvta.to.shared.u64 t, %1; cvt.u32.u64 %0, t; }"
        : "=r"(a) : "l"(p));
    return a;
}

#define CP_ASYNC16(dst, src) \
    asm volatile("cp.async.cg.shared.global [%0], [%1], 16;" \
                 :: "r"(dst), "l"(src) : "memory")
#define CP_COMMIT() asm volatile("cp.async.commit_group;" ::: "memory")
#define CP_WAIT1()  asm volatile("cp.async.wait_group 1;" ::: "memory")
#define CP_WAIT0()  asm volatile("cp.async.wait_group 0;" ::: "memory")

// ---------------------------------------------------------------------------
// fp16 GEMM (NT), K-chunk = 64, single pass:
//   C[m,n] = sum_k X1[m,k]*W1[n,k] (+ X2*W2 phase) + bias[n]
// Tile 128x128x64/chunk; 8 warps of 32x64; 3-stage cp.async pipeline
// with ONE __syncthreads per chunk; register double-buffered ldmatrix
// fragments; smem rows 144 B (128 data + 16 pad).
// ---------------------------------------------------------------------------
#define ROWB   144
#define PLANE  (128 * ROWB)           // 18432 B
#define NSTAGE 3
#define SMEM_G (NSTAGE * 2 * PLANE)   // 110592 B -> occ 2

struct GArgs {
    const __half *X1, *W1;
    const __half *X2, *W2;
    int K1, K2;
};

__device__ __forceinline__ void load_stage(
    uint32_t sb, const __half* Xh, const __half* Wp,
    int ld, int bm, int bn, int k0, int t)
{
    #pragma unroll
    for (int o = 0; o < 8; ++o) {
        int idx   = t + o * 256;
        int plane = idx >> 10;            // 1024 ops per plane
        int p     = idx & 1023;
        int row   = p >> 3;
        int grp   = p & 7;                // 8 x 16B per 128B row
        uint32_t dst = sb + plane * PLANE + row * ROWB + grp * 16;
        const __half* src = (plane == 0)
            ? Xh + (size_t)(bm + row) * ld + k0 + grp * 8
            : Wp + (size_t)(bn + row) * ld + k0 + grp * 8;
        CP_ASYNC16(dst, src);
    }
}

__device__ __forceinline__ void ld_frags(
    uint32_t sb, int mw, int nw, uint32_t laneoff, uint32_t kb,
    uint32_t* af, uint32_t* bf)
{
    const uint32_t aA = sb + mw * ROWB + laneoff + kb;
    ldm_x4(af + 0, aA);
    ldm_x4(af + 4, aA + 16 * ROWB);
    const uint32_t bA = sb + PLANE + nw * ROWB + laneoff + kb;
    #pragma unroll
    for (int j = 0; j < 4; ++j) ldm_x4(bf + 4 * j, bA + j * 16 * ROWB);
}

__global__ void __launch_bounds__(256, 2) gemm_h_nt(
    GArgs ga,
    const float* __restrict__ bias,
    float* __restrict__ Cf,               // fp32 out (nullable)
    __half* __restrict__ Ch,              // fp16 out (if Cf null)
    int M, int N)
{
    extern __shared__ __align__(16) char smraw[];
    const uint32_t sm0 = smem_u32(smraw);

    const int t    = threadIdx.x;
    const int warp = t >> 5;
    const int lane = t & 31;
    const int bm   = blockIdx.y * 128;
    const int bn   = blockIdx.x * 128;
    const int mw   = (warp & 3) * 32;
    const int nw   = (warp >> 2) * 64;
    const uint32_t laneoff = (lane & 15) * ROWB + (lane >> 4) * 16;

    const int nc1 = ga.K1 / 64;
    const int nch = ga.X2 ? nc1 + ga.K2 / 64 : nc1;

    float acc[2][8][4];
    #pragma unroll
    for (int i = 0; i < 2; ++i)
        #pragma unroll
        for (int j = 0; j < 8; ++j)
            #pragma unroll
            for (int e = 0; e < 4; ++e) acc[i][j][e] = 0.f;

    // Prologue: stages 0, 1
    #pragma unroll
    for (int c = 0; c < 2; ++c) {
        if (c < nch) {
            if (c < nc1)
                load_stage(sm0 + c * 2 * PLANE, ga.X1, ga.W1, ga.K1,
                           bm, bn, c * 64, t);
            else
                load_stage(sm0 + c * 2 * PLANE, ga.X2, ga.W2, ga.K2,
                           bm, bn, (c - nc1) * 64, t);
            CP_COMMIT();
        }
    }

    uint32_t af[2][8], bf[2][16];

    for (int c = 0; c < nch; ++c) {
        if (c + 2 <= nch) CP_WAIT1(); else CP_WAIT0();
        __syncthreads();          // single barrier per chunk

        const uint32_t sb = sm0 + (c % NSTAGE) * 2 * PLANE;

        // k-step register pipeline: prefetch ks+1 while issuing mma for ks
        ld_frags(sb, mw, nw, laneoff, 0, af[0], bf[0]);
        #pragma unroll
        for (int ks = 0; ks < 4; ++ks) {
            const int cur = ks & 1;
            if (ks < 3)
                ld_frags(sb, mw, nw, laneoff, (ks + 1) * 32,
                         af[cur ^ 1], bf[cur ^ 1]);
            #pragma unroll
            for (int i = 0; i < 2; ++i) {
                const uint32_t* ah = af[cur] + 4 * i;
                #pragma unroll
                for (int j8 = 0; j8 < 8; ++j8) {
                    uint32_t b0 = bf[cur][4 * (j8 >> 1) + (j8 & 1)];
                    uint32_t b1 = bf[cur][4 * (j8 >> 1) + (j8 & 1) + 2];
                    mma_f16(acc[i][j8], ah, b0, b1);
                }
            }
        }

        // issue loads for chunk c+2 (race-free: last readers of that buffer
        // finished in chunk c-1, before this chunk's collective sync)
        if (c + 2 < nch) {
            const int cn = c + 2;
            const uint32_t db = sm0 + (cn % NSTAGE) * 2 * PLANE;
            if (cn < nc1)
                load_stage(db, ga.X1, ga.W1, ga.K1, bm, bn, cn * 64, t);
            else
                load_stage(db, ga.X2, ga.W2, ga.K2, bm, bn,
                           (cn - nc1) * 64, t);
            CP_COMMIT();
        }
    }

    // Epilogue
    const int g = lane >> 2;
    const int q = lane & 3;
    #pragma unroll
    for (int i = 0; i < 2; ++i) {
        #pragma unroll
        for (int j8 = 0; j8 < 8; ++j8) {
            const int r0  = bm + mw + 16 * i + g;
            const int col = bn + nw + 8 * j8 + 2 * q;
            const float b0v = bias ? bias[col]     : 0.f;
            const float b1v = bias ? bias[col + 1] : 0.f;
            float v00 = acc[i][j8][0] + b0v, v01 = acc[i][j8][1] + b1v;
            float v10 = acc[i][j8][2] + b0v, v11 = acc[i][j8][3] + b1v;
            if (Cf) {
                *(float2*)&Cf[(size_t)r0 * N + col]       = make_float2(v00, v01);
                *(float2*)&Cf[(size_t)(r0 + 8) * N + col] = make_float2(v10, v11);
            } else {
                *(__half2*)&Ch[(size_t)r0 * N + col]       = __floats2half2_rn(v00, v01);
                *(__half2*)&Ch[(size_t)(r0 + 8) * N + col] = __floats2half2_rn(v10, v11);
            }
        }
    }
}

// ---------------------------------------------------------------------------
// Fused converter: s,t fp32 -> fp16 in one launch
// ---------------------------------------------------------------------------
__global__ void cvt_pair32to16(__half* __restrict__ h0, const float* __restrict__ s0,
                               __half* __restrict__ h1, const float* __restrict__ s1,
                               int n)
{
    int i = (blockIdx.x * blockDim.x + threadIdx.x) * 4;
    if (i >= n) return;
    float4 a = *(const float4*)&s0[i];
    *(__half2*)&h0[i]     = __floats2half2_rn(a.x, a.y);
    *(__half2*)&h0[i + 2] = __floats2half2_rn(a.z, a.w);
    float4 b = *(const float4*)&s1[i];
    *(__half2*)&h1[i]     = __floats2half2_rn(b.x, b.y);
    *(__half2*)&h1[i + 2] = __floats2half2_rn(b.z, b.w);
}

__global__ void cvt32to16(__half* __restrict__ h, const float* __restrict__ s, int n)
{
    int i = (blockIdx.x * blockDim.x + threadIdx.x) * 4;
    if (i >= n) return;
    float4 v = *(const float4*)&s[i];
    *(__half2*)&h[i]     = __floats2half2_rn(v.x, v.y);
    *(__half2*)&h[i + 2] = __floats2half2_rn(v.z, v.w);
}

// ---------------------------------------------------------------------------
// Transpose (fp32 in -> fp16 out), once for bk_W
// ---------------------------------------------------------------------------
__global__ void transpose_h_kernel(__half* __restrict__ out,
                                   const float* __restrict__ in,
                                   int Rrows, int Ccols)
{
    __shared__ float tile[32][33];
    int x = blockIdx.x * 32 + threadIdx.x;
    int y = blockIdx.y * 32 + threadIdx.y;
    #pragma unroll
    for (int i = 0; i < 4; ++i)
        tile[threadIdx.y + 8 * i][threadIdx.x] = in[(size_t)(y + 8 * i) * Ccols + x];
    __syncthreads();
    x = blockIdx.y * 32 + threadIdx.x;
    y = blockIdx.x * 32 + threadIdx.y;
    #pragma unroll
    for (int i = 0; i < 4; ++i)
        out[(size_t)(y + 8 * i) * Rrows + x] =
            __float2half_rn(tile[threadIdx.x][threadIdx.y + 8 * i]);
}

// ---------------------------------------------------------------------------
// Combined prep: Ah = qk_W[:, :512] @ q_W ; Bmh = qk_W[:, 512:] @ k_W
// fp32 SIMT GEMM (NN), fp16 out. Grid y: [0,4) -> Ah, [4,8) -> Bmh.
// ---------------------------------------------------------------------------
#define BM 128
#define BN 128
#define BK 16

__global__ void __launch_bounds__(256, 2) prep_weights_kernel(
    __half* __restrict__ CA, __half* __restrict__ CB,
    const float* __restrict__ qk_W,
    const float* __restrict__ q_W, const float* __restrict__ k_W)
{
    const int half  = blockIdx.y >> 2;           // 0: A, 1: Bm
    const int by    = blockIdx.y & 3;
    __half* C       = half ? CB : CA;
    const float* X  = half ? qk_W + DA : qk_W;   // (512, 512) view, ld = 1024
    const float* W  = half ? k_W : q_W;          // (512, 1024) -> used NN: W[k*N+n]
    const int N = DHID, K = DA, ldx = 2 * DA;

    __shared__ float As[BK][BM];
    __shared__ float Bs[BK][BN];
    const int t  = threadIdx.x;
    const int bm = by * BM;
    const int bn = blockIdx.x * BN;

    float acc[8][8];
    #pragma unroll
    for (int i = 0; i < 8; ++i)
        #pragma unroll
        for (int j = 0; j < 8; ++j) acc[i][j] = 0.f;

    const int lrow = t >> 2;
    const int lc4  = (t & 3) * 4;
    const int wk   = t >> 5;
    const int wn4  = (t & 31) * 4;

    for (int k0 = 0; k0 < K; k0 += BK) {
        #pragma unroll
        for (int h = 0; h < 2; ++h) {
            int row = lrow + h * 64;
            float4 v = *(const float4*)&X[(size_t)(bm + row) * ldx + k0 + lc4];
            As[lc4 + 0][row] = v.x;
            As[lc4 + 1][row] = v.y;
            As[lc4 + 2][row] = v.z;
            As[lc4 + 3][row] = v.w;
            int k = wk + h * 8;
            float4 w = *(const float4*)&W[(size_t)(k0 + k) * N + bn + wn4];
            *(float4*)&Bs[k][wn4] = w;
        }
        __syncthreads();
        const int m8 = (t >> 4) * 8;
        const int n8 = (t & 15) * 8;
        #pragma unroll
        for (int kk = 0; kk < BK; ++kk) {
            float a[8], b[8];
            *(float4*)&a[0] = *(const float4*)&As[kk][m8];
            *(float4*)&a[4] = *(const float4*)&As[kk][m8 + 4];
            *(float4*)&b[0] = *(const float4*)&Bs[kk][n8];
            *(float4*)&b[4] = *(const float4*)&Bs[kk][n8 + 4];
            #pragma unroll
            for (int i = 0; i < 8; ++i)
                #pragma unroll
                for (int j = 0; j < 8; ++j)
                    acc[i][j] += a[i] * b[j];
        }
        __syncthreads();
    }

    const int m0 = bm + (t >> 4) * 8;
    const int n0 = bn + (t & 15) * 8;
    #pragma unroll
    for (int i = 0; i < 8; ++i) {
        __half2 h0 = __floats2half2_rn(acc[i][0], acc[i][1]);
        __half2 h1 = __floats2half2_rn(acc[i][2], acc[i][3]);
        __half2 h2 = __floats2half2_rn(acc[i][4], acc[i][5]);
        __half2 h3 = __floats2half2_rn(acc[i][6], acc[i][7]);
        __half* dst = &C[(size_t)(m0 + i) * N + n0];
        *(__half2*)(dst + 0) = h0;
        *(__half2*)(dst + 2) = h1;
        *(__half2*)(dst + 4) = h2;
        *(__half2*)(dst + 6) = h3;
    }
}

// ---------------------------------------------------------------------------
// Fused bias: c[i] = sum_j qk_W[i,j]*q_b[j] + qk_W[i,512+j]*k_b[j] + qk_b[i]
// ---------------------------------------------------------------------------
__global__ void fuse_bias_kernel(float* __restrict__ c,
                                 const float* __restrict__ qk_W,
                                 const float* __restrict__ q_b,
                                 const float* __restrict__ k_b,
                                 const float* __restrict__ qk_b)
{
    int i = blockIdx.x * blockDim.x + threadIdx.x;
    if (i >= DA) return;
    float s = qk_b[i];
    const float* row = qk_W + (size_t)i * (2 * DA);
    for (int j = 0; j < DA; ++j)
        s += row[j] * q_b[j] + row[DA + j] * k_b[j];
    c[i] = s;
}

// ---------------------------------------------------------------------------
// Attention: one block per l. u fp16 in; scores -> softmax -> y (fp16)
// ---------------------------------------------------------------------------
#define SS_LD 65

__global__ void __launch_bounds__(256) attention_kernel(
    const __half* __restrict__ u,     // (B*L, 1024) fp16
    const float* __restrict__ basis,  // (L, R, 1024)
    __half* __restrict__ yh)
{
    extern __shared__ float smf[];
    float* u_s = smf;                      // 16 * 1024 fp32
    float* s_s = smf + BB * DHID;          // 16 * SS_LD

    const int l    = blockIdx.x;
    const int t    = threadIdx.x;
    const int warp = t >> 5;
    const int lane = t & 31;
    const float scale = 0.044194173824159216f;  // 1/sqrt(512)

    for (int it = 0; it < 8; ++it) {
        int idx = t + it * 256;
        int b   = idx >> 7;
        int d8  = (idx & 127) * 8;
        uint4 raw = *(const uint4*)&u[((size_t)b * LL + l) * DHID + d8];
        const __half2* hp = (const __half2*)&raw;
        float* dst = &u_s[b * DHID + d8];
        #pragma unroll
        for (int k = 0; k < 4; ++k) {
            float2 f = __half22float2(hp[k]);
            dst[2 * k]     = f.x;
            dst[2 * k + 1] = f.y;
        }
    }
    __syncthreads();

    const float* basl = basis + (size_t)l * RR * DHID;

    for (int rr = 0; rr < 8; ++rr) {
        int r = warp * 8 + rr;
        const float* brow = basl + (size_t)r * DHID;
        float bas[32];
        #pragma unroll
        for (int i = 0; i < 32; ++i) bas[i] = brow[lane + 32 * i];
        #pragma unroll
        for (int b = 0; b < BB; ++b) {
            float p = 0.f;
            const float* ur = &u_s[b * DHID];
            #pragma unroll
            for (int i = 0; i < 32; ++i) p += bas[i] * ur[lane + 32 * i];
            #pragma unroll
            for (int o = 16; o; o >>= 1) p += __shfl_xor_sync(0xffffffffu, p, o);
            if (lane == 0) s_s[b * SS_LD + r] = p * scale;
        }
    }
    __syncthreads();

    {
        int b0 = warp * 2;
        #pragma unroll
        for (int bi = 0; bi < 2; ++bi) {
            int b = b0 + bi;
            float v0 = s_s[b * SS_LD + lane];
            float v1 = s_s[b * SS_LD + lane + 32];
            float mx = fmaxf(v0, v1);
            #pragma unroll
            for (int o = 16; o; o >>= 1) mx = fmaxf(mx, __shfl_xor_sync(0xffffffffu, mx, o));
            float e0 = __expf(v0 - mx);
            float e1 = __expf(v1 - mx);
            float sum = e0 + e1;
            #pragma unroll
            for (int o = 16; o; o >>= 1) sum += __shfl_xor_sync(0xffffffffu, sum, o);
            float inv = 1.f / sum;
            s_s[b * SS_LD + lane]      = e0 * inv;
            s_s[b * SS_LD + lane + 32] = e1 * inv;
        }
    }
    __syncthreads();

    for (int i = 0; i < 4; ++i) {
        int d = i * 256 + t;
        float acc[BB];
        #pragma unroll
        for (int b = 0; b < BB; ++b) acc[b] = 0.f;
        #pragma unroll 4
        for (int r = 0; r < RR; ++r) {
            float bv = basl[(size_t)r * DHID + d];
            #pragma unroll
            for (int b = 0; b < BB; ++b)
                acc[b] += s_s[b * SS_LD + r] * bv;
        }
        #pragma unroll
        for (int b = 0; b < BB; ++b)
            yh[((size_t)b * LL + l) * DHID + d] = __float2half_rn(acc[b]);
    }
}

// ---------------------------------------------------------------------------
// Launch
// ---------------------------------------------------------------------------
extern "C" void kernel_launch(void* const* d_in, const int* in_sizes, int n_in,
                              void* d_out, int out_size)
{
    const float* s_emb  = (const float*)d_in[0];
    const float* t_emb  = (const float*)d_in[1];
    const float* basis  = (const float*)d_in[2];
    const float* q_W    = (const float*)d_in[3];
    const float* q_b    = (const float*)d_in[4];
    const float* k_W    = (const float*)d_in[5];
    const float* k_b    = (const float*)d_in[6];
    const float* qk_W   = (const float*)d_in[7];
    const float* qk_b   = (const float*)d_in[8];
    const float* bk_W   = (const float*)d_in[9];
    // d_in[10] = bk_b : provably unused (softmax shift invariance)
    const float* bv_W   = (const float*)d_in[11];
    const float* bv_b   = (const float*)d_in[12];
    float* out = (float*)d_out;

    float  *p_c;
    __half *p_sh, *p_th, *p_qh, *p_uh, *p_yh;
    __half *p_Ah, *p_Bmh, *p_bkTh, *p_bvh;
    cudaGetSymbolAddress((void**)&p_c,    g_c);
    cudaGetSymbolAddress((void**)&p_sh,   g_sh);
    cudaGetSymbolAddress((void**)&p_th,   g_th);
    cudaGetSymbolAddress((void**)&p_qh,   g_qh);
    cudaGetSymbolAddress((void**)&p_uh,   g_uh);
    cudaGetSymbolAddress((void**)&p_yh,   g_yh);
    cudaGetSymbolAddress((void**)&p_Ah,   g_Ah);
    cudaGetSymbolAddress((void**)&p_Bmh,  g_Bmh);
    cudaGetSymbolAddress((void**)&p_bkTh, g_bkTh);
    cudaGetSymbolAddress((void**)&p_bvh,  g_bvh);

    const int att_smem = (BB * DHID + BB * SS_LD) * (int)sizeof(float);
    cudaFuncSetAttribute(attention_kernel,
                         cudaFuncAttributeMaxDynamicSharedMemorySize, att_smem);
    cudaFuncSetAttribute(gemm_h_nt,
                         cudaFuncAttributeMaxDynamicSharedMemorySize, SMEM_G);

    // launch 0: s,t -> fp16
    const int ne = MTOT * DHID;
    cvt_pair32to16<<<ne / 4 / 256, 256>>>(p_sh, s_emb, p_th, t_emb, ne);

    // launch 1: fused projection matrices Ah, Bmh (fp16 out)
    {
        dim3 grid(DHID / BN, 8);
        prep_weights_kernel<<<grid, 256>>>(p_Ah, p_Bmh, qk_W, q_W, k_W);
    }

    // launch 2: fused bias
    fuse_bias_kernel<<<1, DA>>>(p_c, qk_W, q_b, k_b, qk_b);

    // launch 3 (ncu capture slot): qk = s@A^T + t@Bm^T + c -> fp16
    {
        GArgs ga = { p_sh, p_Ah, p_th, p_Bmh, DHID, DHID };
        dim3 grid(DA / 128, MTOT / 128);
        gemm_h_nt<<<grid, 256, SMEM_G>>>(ga, p_c, nullptr, p_qh, MTOT, DA);
    }

    // launch 4: bk_W transpose -> fp16
    {
        dim3 tg(DHID / 32, DA / 32);
        transpose_h_kernel<<<tg, dim3(32, 8)>>>(p_bkTh, bk_W, DA, DHID);
    }

    // launch 5: bv_W -> fp16
    cvt32to16<<<(DA * DHID) / 4 / 256, 256>>>(p_bvh, bv_W, DA * DHID);

    // launch 6: u = qk @ bkT^T -> fp16
    {
        GArgs ga = { p_qh, p_bkTh, nullptr, nullptr, DA, 0 };
        dim3 grid(DHID / 128, MTOT / 128);
        gemm_h_nt<<<grid, 256, SMEM_G>>>(ga, nullptr, nullptr, p_uh, MTOT, DHID);
    }

    // launch 7: attention
    attention_kernel<<<LL, 256, att_smem>>>(p_uh, basis, p_yh);

    // launch 8: z = y @ bv_W^T + bv_b -> fp32 out
    {
        GArgs ga = { p_yh, p_bvh, nullptr, nullptr, DHID, 0 };
        dim3 grid(DA / 128, MTOT / 128);
        gemm_h_nt<<<grid, 256, SMEM_G>>>(ga, bv_b, out, nullptr, MTOT, DA);
    }
}